// round 8
// baseline (speedup 1.0000x reference)
#include <cuda_runtime.h>
#include <math.h>
#include <stdint.h>

// Problem constants
#define BB 4
#define SS 1024
#define DD 1024
#define HH 16
#define HDD 64
#define EE 8
#define FF 4096
#define NTOK 4096      // B*S
#define NSLOT 8192     // NTOK * K(=2)
#define RMS_EPS 1e-6f
#define ATT_SCALE 0.125f   // 1/sqrt(64)

// ---------------- scratch (static device globals; no runtime allocation) ----
__device__ float g_xn[NTOK * DD];
__device__ float g_qh[NTOK * DD];
__device__ float g_kh[NTOK * DD];
__device__ float g_vh[NTOK * DD];
__device__ float g_att[NTOK * DD];
__device__ float g_h[NTOK * DD];
__device__ float g_hidden[(size_t)NSLOT * FF];
__device__ float g_ypair[(size_t)NSLOT * DD];
__device__ float g_gate[NSLOT];
__device__ int   g_expcnt[EE];
__device__ int   g_expslots[EE * NTOK];

// ---------------- helpers ---------------------------------------------------
__device__ __forceinline__ void mma_tf32(float* c, const uint32_t* a, const uint32_t* b) {
    asm volatile(
        "mma.sync.aligned.m16n8k8.row.col.f32.tf32.tf32.f32 "
        "{%0,%1,%2,%3}, {%4,%5,%6,%7}, {%8,%9}, {%0,%1,%2,%3};\n"
        : "+f"(c[0]), "+f"(c[1]), "+f"(c[2]), "+f"(c[3])
        : "r"(a[0]), "r"(a[1]), "r"(a[2]), "r"(a[3]), "r"(b[0]), "r"(b[1]));
}

__device__ __forceinline__ void cp16(uint32_t dst, const void* src) {
    asm volatile("cp.async.cg.shared.global [%0], [%1], 16;\n"
                 :: "r"(dst), "l"(src));
}
__device__ __forceinline__ void cp16z(uint32_t dst, const void* src, int ok) {
    asm volatile("cp.async.cg.shared.global [%0], [%1], 16, %2;\n"
                 :: "r"(dst), "l"(src), "r"(ok ? 16 : 0));
}
__device__ __forceinline__ void cp_commit() {
    asm volatile("cp.async.commit_group;\n" ::: "memory");
}
template <int N>
__device__ __forceinline__ void cp_wait() {
    asm volatile("cp.async.wait_group %0;\n" :: "n"(N) : "memory");
}

// Smem tiles: 128x32 (A / full-width B) and 64x32 (half-width B), stride 36.
#define TSTR 36
#define TILEW (128 * TSTR)                    // uint32 per 128-row tile
#define TILEB (64 * TSTR)                     // uint32 per 64-row tile
#define PROJ_SMEM  (6 * TILEW * 4)            // S=3 x (A + B128) = 110592 B
#define W13_STAGE  (TILEW + 2 * TILEB)        // u32 per stage (A + B1 + B3)
#define W13_SMEM   (3 * W13_STAGE * 4)        // 110592 B
#define W2_STAGE   (TILEW + TILEB)            // u32 per stage (A + B64)
#define W2_SMEM    (3 * W2_STAGE * 4)         // 82944 B

// ---------------- RMSNorm ---------------------------------------------------
__global__ __launch_bounds__(256) void rmsnorm_kernel(
    const float* __restrict__ x, const float* __restrict__ w,
    float* __restrict__ out)
{
    int t = blockIdx.x;
    const float4* xr = (const float4*)(x + (size_t)t * DD);
    float4 v = xr[threadIdx.x];
    float ss = v.x * v.x + v.y * v.y + v.z * v.z + v.w * v.w;
    #pragma unroll
    for (int o = 16; o; o >>= 1) ss += __shfl_xor_sync(0xffffffffu, ss, o);
    __shared__ float sh[8];
    __shared__ float stot;
    int warp = threadIdx.x >> 5;
    if ((threadIdx.x & 31) == 0) sh[warp] = ss;
    __syncthreads();
    if (threadIdx.x == 0) {
        float s = 0.f;
        #pragma unroll
        for (int i = 0; i < 8; i++) s += sh[i];
        stot = rsqrtf(s / (float)DD + RMS_EPS);
    }
    __syncthreads();
    float sc = stot;
    float4 wv = ((const float4*)w)[threadIdx.x];
    float4 o;
    o.x = v.x * sc * wv.x; o.y = v.y * sc * wv.y;
    o.z = v.z * sc * wv.z; o.w = v.w * sc * wv.w;
    ((float4*)(out + (size_t)t * DD))[threadIdx.x] = o;
}

// ---- 3-stage issue macro for dense proj (A + B 128-row tiles) --------------
#define ISSUE_PROJ(tile, st) do {                                              \
    const int koff_ = (tile) * 32;                                             \
    const uint32_t ao_ = (uint32_t)(st) * TILEW * 4;                           \
    _Pragma("unroll")                                                          \
    for (int i_ = 0; i_ < 4; i_++) {                                           \
        cp16(dA0 + ao_ + i_ * 32 * TSTR * 4, Ap + (size_t)i_ * 32 * Kk + koff_); \
        cp16(dB0 + ao_ + i_ * 32 * TSTR * 4, Wp + (size_t)i_ * 32 * Kk + koff_); \
    }                                                                          \
    cp_commit();                                                               \
} while (0)

// Shared compute step for 128x128 tile (acc[4][4][4])
#define COMPUTE_TILE(Ab, Bb)                                                   \
    _Pragma("unroll")                                                          \
    for (int k8 = 0; k8 < 4; k8++) {                                           \
        int kb = k8 * 8;                                                       \
        uint32_t bf[4][2];                                                     \
        _Pragma("unroll")                                                      \
        for (int ni = 0; ni < 4; ni++) {                                       \
            int n = warpN * 32 + ni * 8 + g;                                   \
            bf[ni][0] = (Bb)[n * TSTR + kb + t];                               \
            bf[ni][1] = (Bb)[n * TSTR + kb + t + 4];                           \
        }                                                                      \
        _Pragma("unroll")                                                      \
        for (int mi = 0; mi < 4; mi++) {                                       \
            int m = warpM * 64 + mi * 16 + g;                                  \
            uint32_t af[4];                                                    \
            af[0] = (Ab)[m * TSTR + kb + t];                                   \
            af[1] = (Ab)[(m + 8) * TSTR + kb + t];                             \
            af[2] = (Ab)[m * TSTR + kb + t + 4];                               \
            af[3] = (Ab)[(m + 8) * TSTR + kb + t + 4];                         \
            _Pragma("unroll")                                                  \
            for (int ni = 0; ni < 4; ni++)                                     \
                mma_tf32(acc[mi][ni], af, bf[ni]);                             \
        }                                                                      \
    }

// ---------------- dense proj GEMM, 3-stage pipeline, 1 barrier/tile ---------
__global__ __launch_bounds__(256) void gemm_mma_proj3(
    const float* __restrict__ A, const float* __restrict__ W,
    const float* __restrict__ resid, float* __restrict__ C,
    int Kk, int Nn)
{
    extern __shared__ uint32_t smbuf[];
    uint32_t* As = smbuf;                  // [3][TILEW]
    uint32_t* Bs = smbuf + 3 * TILEW;      // [3][TILEW]
    const uint32_t smA = (uint32_t)__cvta_generic_to_shared(As);
    const uint32_t smB = (uint32_t)__cvta_generic_to_shared(Bs);

    const int tid = threadIdx.x;
    const int lane = tid & 31, warp = tid >> 5;
    const int warpM = warp >> 2, warpN = warp & 3;
    const int g = lane >> 2, t = lane & 3;
    const int m0 = blockIdx.y * 128, n0 = blockIdx.x * 128;
    float acc[4][4][4] = {};

    const int lrow = tid >> 3;
    const int lkf = (tid & 7) * 4;
    const float* Ap = A + (size_t)(m0 + lrow) * Kk + lkf;
    const float* Wp = W + (size_t)(n0 + lrow) * Kk + lkf;
    const uint32_t dA0 = smA + (lrow * TSTR + lkf) * 4;
    const uint32_t dB0 = smB + (lrow * TSTR + lkf) * 4;

    const int nt = Kk >> 5;
    ISSUE_PROJ(0, 0);
    ISSUE_PROJ(1, 1);

    for (int kt = 0; kt < nt; kt++) {
        if (kt + 1 < nt) cp_wait<1>(); else cp_wait<0>();
        __syncthreads();
        if (kt + 2 < nt) {
            ISSUE_PROJ(kt + 2, (kt + 2) % 3);
        }
        const uint32_t* Ab = As + (kt % 3) * TILEW;
        const uint32_t* Bb = Bs + (kt % 3) * TILEW;
        COMPUTE_TILE(Ab, Bb);
    }

    #pragma unroll
    for (int mi = 0; mi < 4; mi++) {
        int r0 = m0 + warpM * 64 + mi * 16 + g;
        #pragma unroll
        for (int ni = 0; ni < 4; ni++) {
            int c = n0 + warpN * 32 + ni * 8 + 2 * t;
            size_t i0 = (size_t)r0 * Nn + c;
            size_t i1 = i0 + (size_t)8 * Nn;
            float2 v0 = make_float2(acc[mi][ni][0], acc[mi][ni][1]);
            float2 v1 = make_float2(acc[mi][ni][2], acc[mi][ni][3]);
            if (resid) {
                float2 r = *(const float2*)(resid + i0); v0.x += r.x; v0.y += r.y;
                r = *(const float2*)(resid + i1); v1.x += r.x; v1.y += r.y;
            }
            *(float2*)(C + i0) = v0;
            *(float2*)(C + i1) = v1;
        }
    }
}

// ---------------- fused QKV projection --------------------------------------
__global__ __launch_bounds__(256) void gemm_mma_qkv(
    const float* __restrict__ A,
    const float* __restrict__ wq, const float* __restrict__ wk,
    const float* __restrict__ wv,
    float* __restrict__ qo, float* __restrict__ ko, float* __restrict__ vo)
{
    extern __shared__ uint32_t smbuf[];
    uint32_t* As = smbuf;
    uint32_t* Bs = smbuf + 3 * TILEW;
    const uint32_t smA = (uint32_t)__cvta_generic_to_shared(As);
    const uint32_t smB = (uint32_t)__cvta_generic_to_shared(Bs);

    const int tid = threadIdx.x;
    const int lane = tid & 31, warp = tid >> 5;
    const int warpM = warp >> 2, warpN = warp & 3;
    const int g = lane >> 2, t = lane & 3;
    const int m0 = blockIdx.y * 128;
    const int n0t = blockIdx.x * 128;

    const float* W; float* C; int n0;
    if (n0t < DD)            { W = wq; C = qo; n0 = n0t; }
    else if (n0t < 2 * DD)   { W = wk; C = ko; n0 = n0t - DD; }
    else                     { W = wv; C = vo; n0 = n0t - 2 * DD; }

    const int Kk = DD;
    float acc[4][4][4] = {};

    const int lrow = tid >> 3;
    const int lkf = (tid & 7) * 4;
    const float* Ap = A + (size_t)(m0 + lrow) * Kk + lkf;
    const float* Wp = W + (size_t)(n0 + lrow) * Kk + lkf;
    const uint32_t dA0 = smA + (lrow * TSTR + lkf) * 4;
    const uint32_t dB0 = smB + (lrow * TSTR + lkf) * 4;

    const int nt = Kk >> 5;
    ISSUE_PROJ(0, 0);
    ISSUE_PROJ(1, 1);

    for (int kt = 0; kt < nt; kt++) {
        if (kt + 1 < nt) cp_wait<1>(); else cp_wait<0>();
        __syncthreads();
        if (kt + 2 < nt) {
            ISSUE_PROJ(kt + 2, (kt + 2) % 3);
        }
        const uint32_t* Ab = As + (kt % 3) * TILEW;
        const uint32_t* Bb = Bs + (kt % 3) * TILEW;
        COMPUTE_TILE(Ab, Bb);
    }

    #pragma unroll
    for (int mi = 0; mi < 4; mi++) {
        int r0 = m0 + warpM * 64 + mi * 16 + g;
        #pragma unroll
        for (int ni = 0; ni < 4; ni++) {
            int c = n0 + warpN * 32 + ni * 8 + 2 * t;
            size_t i0 = (size_t)r0 * DD + c;
            size_t i1 = i0 + (size_t)8 * DD;
            *(float2*)(C + i0) = make_float2(acc[mi][ni][0], acc[mi][ni][1]);
            *(float2*)(C + i1) = make_float2(acc[mi][ni][2], acc[mi][ni][3]);
        }
    }
}

// ---------------- fused w1+w3 expert GEMM (3-stage, 1 barrier/tile) ---------
// hidden[slot, n] = silu(A@w1^T) * (A@w3^T).
// Stage layout: [A(128x32) | B1(64x32) | B3(64x32)], 3 stages.
// grid (FF/64, NTOK/128, E), block 256. Warp grid 2(M) x 4(N): 64x16 per B.
#define ISSUE_W13(tile, st) do {                                               \
    const int koff_ = (tile) * 32;                                             \
    const uint32_t ao_ = (uint32_t)(st) * W13_STAGE * 4;                       \
    _Pragma("unroll")                                                          \
    for (int i_ = 0; i_ < 4; i_++)                                             \
        cp16z(dA0 + ao_ + i_ * 32 * TSTR * 4, arp[i_] + koff_, aok[i_]);       \
    _Pragma("unroll")                                                          \
    for (int i_ = 0; i_ < 2; i_++) {                                           \
        cp16(dB10 + ao_ + i_ * 32 * TSTR * 4, Wp1 + (size_t)i_ * 32 * DD + koff_); \
        cp16(dB30 + ao_ + i_ * 32 * TSTR * 4, Wp3 + (size_t)i_ * 32 * DD + koff_); \
    }                                                                          \
    cp_commit();                                                               \
} while (0)

__global__ __launch_bounds__(256) void gemm_mma_w13(
    const float* __restrict__ A,
    const float* __restrict__ W1base, const float* __restrict__ W3base)
{
    const int e = blockIdx.z;
    const int count = g_expcnt[e];
    const int m0 = blockIdx.y * 128;
    if (m0 >= count) return;

    extern __shared__ uint32_t smbuf[];     // [3][W13_STAGE]
    __shared__ int srow[128];
    const uint32_t smBase = (uint32_t)__cvta_generic_to_shared(smbuf);

    const int tid = threadIdx.x;
    if (tid < 128) {
        int r = m0 + tid;
        srow[tid] = (r < count) ? g_expslots[e * NTOK + r] : -1;
    }
    __syncthreads();

    const int lane = tid & 31, warp = tid >> 5;
    const int warpM = warp >> 2, warpN = warp & 3;
    const int g = lane >> 2, t = lane & 3;
    const int n0 = blockIdx.x * 64;
    const float* W1 = W1base + (size_t)e * FF * DD;
    const float* W3 = W3base + (size_t)e * FF * DD;
    float acc1[4][2][4] = {};
    float acc3[4][2][4] = {};

    const int lrow = tid >> 3;
    const int lkf = (tid & 7) * 4;

    const float* arp[4];
    int aok[4];
    #pragma unroll
    for (int i = 0; i < 4; i++) {
        int s = srow[lrow + i * 32];
        aok[i] = (s >= 0);
        int arow = (s >= 0) ? (s >> 1) : 0;
        arp[i] = A + (size_t)arow * DD + lkf;
    }
    const float* Wp1 = W1 + (size_t)(n0 + lrow) * DD + lkf;
    const float* Wp3 = W3 + (size_t)(n0 + lrow) * DD + lkf;
    const uint32_t dA0  = smBase + (lrow * TSTR + lkf) * 4;
    const uint32_t dB10 = smBase + (TILEW + lrow * TSTR + lkf) * 4;
    const uint32_t dB30 = smBase + (TILEW + TILEB + lrow * TSTR + lkf) * 4;

    const int nt = DD >> 5;   // 32
    ISSUE_W13(0, 0);
    ISSUE_W13(1, 1);

    for (int kt = 0; kt < nt; kt++) {
        if (kt + 1 < nt) cp_wait<1>(); else cp_wait<0>();
        __syncthreads();
        if (kt + 2 < nt) {
            ISSUE_W13(kt + 2, (kt + 2) % 3);
        }
        const uint32_t* Sb  = smbuf + (kt % 3) * W13_STAGE;
        const uint32_t* Ab  = Sb;
        const uint32_t* B1b = Sb + TILEW;
        const uint32_t* B3b = Sb + TILEW + TILEB;
        #pragma unroll
        for (int k8 = 0; k8 < 4; k8++) {
            int kb = k8 * 8;
            uint32_t bf1[2][2], bf3[2][2];
            #pragma unroll
            for (int ni = 0; ni < 2; ni++) {
                int n = warpN * 16 + ni * 8 + g;
                bf1[ni][0] = B1b[n * TSTR + kb + t];
                bf1[ni][1] = B1b[n * TSTR + kb + t + 4];
                bf3[ni][0] = B3b[n * TSTR + kb + t];
                bf3[ni][1] = B3b[n * TSTR + kb + t + 4];
            }
            #pragma unroll
            for (int mi = 0; mi < 4; mi++) {
                int m = warpM * 64 + mi * 16 + g;
                uint32_t af[4];
                af[0] = Ab[m * TSTR + kb + t];
                af[1] = Ab[(m + 8) * TSTR + kb + t];
                af[2] = Ab[m * TSTR + kb + t + 4];
                af[3] = Ab[(m + 8) * TSTR + kb + t + 4];
                #pragma unroll
                for (int ni = 0; ni < 2; ni++) {
                    mma_tf32(acc1[mi][ni], af, bf1[ni]);
                    mma_tf32(acc3[mi][ni], af, bf3[ni]);
                }
            }
        }
    }

    #pragma unroll
    for (int mi = 0; mi < 4; mi++) {
        int mloc0 = warpM * 64 + mi * 16 + g;
        #pragma unroll
        for (int half = 0; half < 2; half++) {
            int mloc = mloc0 + half * 8;
            int s = srow[mloc];
            if (s < 0) continue;
            #pragma unroll
            for (int ni = 0; ni < 2; ni++) {
                int c = n0 + warpN * 16 + ni * 8 + 2 * t;
                float h1x = acc1[mi][ni][half * 2],     h1y = acc1[mi][ni][half * 2 + 1];
                float h3x = acc3[mi][ni][half * 2],     h3y = acc3[mi][ni][half * 2 + 1];
                float2 o;
                o.x = (h1x / (1.f + expf(-h1x))) * h3x;
                o.y = (h1y / (1.f + expf(-h1y))) * h3y;
                *(float2*)(&g_hidden[(size_t)s * FF + c]) = o;
            }
        }
    }
}

// ---------------- w2 expert GEMM (N=64 tiles, 3-stage, 1 barrier/tile) ------
// g_ypair[slot] = hidden[slot] @ w2^T. grid (DD/64, NTOK/128, E), block 256.
#define ISSUE_W2(tile, st) do {                                                \
    const int koff_ = (tile) * 32;                                             \
    const uint32_t ao_ = (uint32_t)(st) * W2_STAGE * 4;                        \
    _Pragma("unroll")                                                          \
    for (int i_ = 0; i_ < 4; i_++)                                             \
        cp16z(dA0 + ao_ + i_ * 32 * TSTR * 4, arp[i_] + koff_, aok[i_]);       \
    _Pragma("unroll")                                                          \
    for (int i_ = 0; i_ < 2; i_++)                                             \
        cp16(dB0 + ao_ + i_ * 32 * TSTR * 4, Wp + (size_t)i_ * 32 * FF + koff_); \
    cp_commit();                                                               \
} while (0)

__global__ __launch_bounds__(256) void gemm_mma_w2(
    const float* __restrict__ A, const float* __restrict__ Wbase)
{
    const int e = blockIdx.z;
    const int count = g_expcnt[e];
    const int m0 = blockIdx.y * 128;
    if (m0 >= count) return;

    extern __shared__ uint32_t smbuf[];     // [3][W2_STAGE]
    __shared__ int srow[128];
    const uint32_t smBase = (uint32_t)__cvta_generic_to_shared(smbuf);

    const int tid = threadIdx.x;
    if (tid < 128) {
        int r = m0 + tid;
        srow[tid] = (r < count) ? g_expslots[e * NTOK + r] : -1;
    }
    __syncthreads();

    const int lane = tid & 31, warp = tid >> 5;
    const int warpM = warp >> 2, warpN = warp & 3;
    const int g = lane >> 2, t = lane & 3;
    const int n0 = blockIdx.x * 64;
    const float* W = Wbase + (size_t)e * DD * FF;
    float acc[4][2][4] = {};

    const int lrow = tid >> 3;
    const int lkf = (tid & 7) * 4;

    const float* arp[4];
    int aok[4];
    #pragma unroll
    for (int i = 0; i < 4; i++) {
        int s = srow[lrow + i * 32];
        aok[i] = (s >= 0);
        int arow = (s >= 0) ? s : 0;
        arp[i] = A + (size_t)arow * FF + lkf;
    }
    const float* Wp = W + (size_t)(n0 + lrow) * FF + lkf;
    const uint32_t dA0 = smBase + (lrow * TSTR + lkf) * 4;
    const uint32_t dB0 = smBase + (TILEW + lrow * TSTR + lkf) * 4;

    const int nt = FF >> 5;    // 128
    ISSUE_W2(0, 0);
    ISSUE_W2(1, 1);

    for (int kt = 0; kt < nt; kt++) {
        if (kt + 1 < nt) cp_wait<1>(); else cp_wait<0>();
        __syncthreads();
        if (kt + 2 < nt) {
            ISSUE_W2(kt + 2, (kt + 2) % 3);
        }
        const uint32_t* Sb = smbuf + (kt % 3) * W2_STAGE;
        const uint32_t* Ab = Sb;
        const uint32_t* Bb = Sb + TILEW;
        #pragma unroll
        for (int k8 = 0; k8 < 4; k8++) {
            int kb = k8 * 8;
            uint32_t bf[2][2];
            #pragma unroll
            for (int ni = 0; ni < 2; ni++) {
                int n = warpN * 16 + ni * 8 + g;
                bf[ni][0] = Bb[n * TSTR + kb + t];
                bf[ni][1] = Bb[n * TSTR + kb + t + 4];
            }
            #pragma unroll
            for (int mi = 0; mi < 4; mi++) {
                int m = warpM * 64 + mi * 16 + g;
                uint32_t af[4];
                af[0] = Ab[m * TSTR + kb + t];
                af[1] = Ab[(m + 8) * TSTR + kb + t];
                af[2] = Ab[m * TSTR + kb + t + 4];
                af[3] = Ab[(m + 8) * TSTR + kb + t + 4];
                #pragma unroll
                for (int ni = 0; ni < 2; ni++)
                    mma_tf32(acc[mi][ni], af, bf[ni]);
            }
        }
    }

    #pragma unroll
    for (int mi = 0; mi < 4; mi++) {
        int mloc0 = warpM * 64 + mi * 16 + g;
        #pragma unroll
        for (int half = 0; half < 2; half++) {
            int mloc = mloc0 + half * 8;
            int s = srow[mloc];
            if (s < 0) continue;
            #pragma unroll
            for (int ni = 0; ni < 2; ni++) {
                int c = n0 + warpN * 16 + ni * 8 + 2 * t;
                *(float2*)(&g_ypair[(size_t)s * DD + c]) =
                    make_float2(acc[mi][ni][half * 2], acc[mi][ni][half * 2 + 1]);
            }
        }
    }
}

// ---------------- RoPE (q and k in place) -----------------------------------
__global__ void rope_kernel(float* __restrict__ qh, float* __restrict__ kh,
                            const float* __restrict__ cosb,
                            const float* __restrict__ sinb)
{
    int idx = blockIdx.x * blockDim.x + threadIdx.x;
    int i = idx & 31;
    int th = idx >> 5;
    int t = th >> 4;
    int s = t & (SS - 1);
    float c = cosb[s * 32 + i], sn = sinb[s * 32 + i];
    size_t base = (size_t)th * HDD + i * 2;
    float xr = qh[base], xi = qh[base + 1];
    qh[base]     = xr * c - xi * sn;
    qh[base + 1] = xr * sn + xi * c;
    xr = kh[base]; xi = kh[base + 1];
    kh[base]     = xr * c - xi * sn;
    kh[base + 1] = xr * sn + xi * c;
}

// ---------------- Flash attention (tf32 tensor cores) -----------------------
#define ASTR 68
#define ATT_SMEM (4 * 64 * ASTR * 4)
__global__ __launch_bounds__(128) void attn_mma_kernel(
    const float* __restrict__ Q, const float* __restrict__ K,
    const float* __restrict__ V, float* __restrict__ O,
    const int* __restrict__ causal_flag)
{
    extern __shared__ float sm[];
    float* Qs = sm;
    float* Ks = Qs + 64 * ASTR;
    float* Vt = Ks + 64 * ASTR;   // transposed: Vt[d][kpos]
    float* Ps = Vt + 64 * ASTR;
    const int qt = blockIdx.x, bh = blockIdx.y;
    const int b = bh >> 4, h = bh & 15;
    const int tid = threadIdx.x;
    const int warp = tid >> 5, lane = tid & 31;
    const int g = lane >> 2, t = lane & 3;
    const int causal = *causal_flag;
    const size_t base = (size_t)b * SS * DD + (size_t)h * HDD;
    const float* Qb = Q + base;
    const float* Kb = K + base;
    const float* Vb = V + base;
    const int q0 = qt * 64;

    {
        int row = tid >> 1;
        int cb = (tid & 1) * 32;
        const float* src = Qb + (size_t)(q0 + row) * DD + cb;
        #pragma unroll
        for (int j = 0; j < 8; j++) {
            float4 v = *(const float4*)(src + j * 4);
            float* d = &Qs[row * ASTR + cb + j * 4];
            d[0] = v.x * ATT_SCALE; d[1] = v.y * ATT_SCALE;
            d[2] = v.z * ATT_SCALE; d[3] = v.w * ATT_SCALE;
        }
    }

    float m_run0 = -1e30f, m_run1 = -1e30f;
    float l_run0 = 0.f, l_run1 = 0.f;
    float Oacc[8][4] = {};
    const int mrow = warp * 16 + g;

    const int ktmax = causal ? qt : (SS / 64 - 1);
    for (int kt = 0; kt <= ktmax; kt++) {
        __syncthreads();
        {
            int row = tid >> 1;
            int cb = (tid & 1) * 32;
            const float* ksrc = Kb + (size_t)(kt * 64 + row) * DD + cb;
            const float* vsrc = Vb + (size_t)(kt * 64 + row) * DD + cb;
            #pragma unroll
            for (int j = 0; j < 8; j++) {
                float4 kv = *(const float4*)(ksrc + j * 4);
                float* d = &Ks[row * ASTR + cb + j * 4];
                d[0] = kv.x; d[1] = kv.y; d[2] = kv.z; d[3] = kv.w;
                float4 vv = *(const float4*)(vsrc + j * 4);
                int c = cb + j * 4;
                Vt[(c + 0) * ASTR + row] = vv.x;
                Vt[(c + 1) * ASTR + row] = vv.y;
                Vt[(c + 2) * ASTR + row] = vv.z;
                Vt[(c + 3) * ASTR + row] = vv.w;
            }
        }
        __syncthreads();

        float sacc[8][4] = {};
        const uint32_t* Qsu = (const uint32_t*)Qs;
        const uint32_t* Ksu = (const uint32_t*)Ks;
        #pragma unroll
        for (int k8 = 0; k8 < 8; k8++) {
            int kb = k8 * 8;
            uint32_t af[4];
            af[0] = Qsu[mrow * ASTR + kb + t];
            af[1] = Qsu[(mrow + 8) * ASTR + kb + t];
            af[2] = Qsu[mrow * ASTR + kb + t + 4];
            af[3] = Qsu[(mrow + 8) * ASTR + kb + t + 4];
            #pragma unroll
            for (int ni = 0; ni < 8; ni++) {
                uint32_t bf[2];
                bf[0] = Ksu[(ni * 8 + g) * ASTR + kb + t];
                bf[1] = Ksu[(ni * 8 + g) * ASTR + kb + t + 4];
                mma_tf32(sacc[ni], af, bf);
            }
        }

        const int row0 = q0 + mrow, row1 = row0 + 8;
        if (causal && kt == qt) {
            #pragma unroll
            for (int ni = 0; ni < 8; ni++) {
                int c0 = kt * 64 + ni * 8 + 2 * t;
                if (c0     > row0) sacc[ni][0] = -1e30f;
                if (c0 + 1 > row0) sacc[ni][1] = -1e30f;
                if (c0     > row1) sacc[ni][2] = -1e30f;
                if (c0 + 1 > row1) sacc[ni][3] = -1e30f;
            }
        }

        float ml0 = -1e30f, ml1 = -1e30f;
        #pragma unroll
        for (int ni = 0; ni < 8; ni++) {
            ml0 = fmaxf(ml0, fmaxf(sacc[ni][0], sacc[ni][1]));
            ml1 = fmaxf(ml1, fmaxf(sacc[ni][2], sacc[ni][3]));
        }
        ml0 = fmaxf(ml0, __shfl_xor_sync(0xffffffffu, ml0, 1));
        ml0 = fmaxf(ml0, __shfl_xor_sync(0xffffffffu, ml0, 2));
        ml1 = fmaxf(ml1, __shfl_xor_sync(0xffffffffu, ml1, 1));
        ml1 = fmaxf(ml1, __shfl_xor_sync(0xffffffffu, ml1, 2));
        float mn0 = fmaxf(m_run0, ml0), mn1 = fmaxf(m_run1, ml1);
        float a0 = expf(m_run0 - mn0), a1 = expf(m_run1 - mn1);
        float ps0 = 0.f, ps1 = 0.f;
        #pragma unroll
        for (int ni = 0; ni < 8; ni++) {
            float p0 = expf(sacc[ni][0] - mn0);
            float p1 = expf(sacc[ni][1] - mn0);
            float p2 = expf(sacc[ni][2] - mn1);
            float p3 = expf(sacc[ni][3] - mn1);
            ps0 += p0 + p1; ps1 += p2 + p3;
            int cl = ni * 8 + 2 * t;
            *(float2*)&Ps[mrow * ASTR + cl]       = make_float2(p0, p1);
            *(float2*)&Ps[(mrow + 8) * ASTR + cl] = make_float2(p2, p3);
        }
        ps0 += __shfl_xor_sync(0xffffffffu, ps0, 1);
        ps0 += __shfl_xor_sync(0xffffffffu, ps0, 2);
        ps1 += __shfl_xor_sync(0xffffffffu, ps1, 1);
        ps1 += __shfl_xor_sync(0xffffffffu, ps1, 2);
        l_run0 = l_run0 * a0 + ps0;
        l_run1 = l_run1 * a1 + ps1;
        m_run0 = mn0; m_run1 = mn1;
        #pragma unroll
        for (int ni = 0; ni < 8; ni++) {
            Oacc[ni][0] *= a0; Oacc[ni][1] *= a0;
            Oacc[ni][2] *= a1; Oacc[ni][3] *= a1;
        }
        __syncwarp();

        const uint32_t* Psu = (const uint32_t*)Ps;
        const uint32_t* Vtu = (const uint32_t*)Vt;
        #pragma unroll
        for (int k8 = 0; k8 < 8; k8++) {
            int kb = k8 * 8;
            uint32_t af[4];
            af[0] = Psu[mrow * ASTR + kb + t];
            af[1] = Psu[(mrow + 8) * ASTR + kb + t];
            af[2] = Psu[mrow * ASTR + kb + t + 4];
            af[3] = Psu[(mrow + 8) * ASTR + kb + t + 4];
            #pragma unroll
            for (int ni = 0; ni < 8; ni++) {
                uint32_t bf[2];
                bf[0] = Vtu[(ni * 8 + g) * ASTR + kb + t];
                bf[1] = Vtu[(ni * 8 + g) * ASTR + kb + t + 4];
                mma_tf32(Oacc[ni], af, bf);
            }
        }
    }

    float i0 = 1.f / l_run0, i1 = 1.f / l_run1;
    const int row0 = q0 + mrow;
    float* dst0 = O + (size_t)(b * SS + row0) * DD + (size_t)h * HDD;
    float* dst1 = dst0 + (size_t)8 * DD;
    #pragma unroll
    for (int ni = 0; ni < 8; ni++) {
        int d = ni * 8 + 2 * t;
        *(float2*)(dst0 + d) = make_float2(Oacc[ni][0] * i0, Oacc[ni][1] * i0);
        *(float2*)(dst1 + d) = make_float2(Oacc[ni][2] * i1, Oacc[ni][3] * i1);
    }
}

// ---------------- router + top-2 --------------------------------------------
__global__ void zero_counts_kernel()
{
    if (threadIdx.x < EE) g_expcnt[threadIdx.x] = 0;
}

__global__ __launch_bounds__(256) void router_kernel(
    const float* __restrict__ xn, const float* __restrict__ rw,
    const float* __restrict__ rb)
{
    int t = blockIdx.x;
    float4 xv = ((const float4*)(xn + (size_t)t * DD))[threadIdx.x];
    float lg[EE];
    #pragma unroll
    for (int e = 0; e < EE; e++) {
        float4 wv = ((const float4*)(rw + (size_t)e * DD))[threadIdx.x];
        lg[e] = xv.x * wv.x + xv.y * wv.y + xv.z * wv.z + xv.w * wv.w;
    }
    #pragma unroll
    for (int o = 16; o; o >>= 1)
        #pragma unroll
        for (int e = 0; e < EE; e++)
            lg[e] += __shfl_xor_sync(0xffffffffu, lg[e], o);
    __shared__ float sh[EE][8];
    int warp = threadIdx.x >> 5;
    if ((threadIdx.x & 31) == 0)
        #pragma unroll
        for (int e = 0; e < EE; e++) sh[e][warp] = lg[e];
    __syncthreads();
    if (threadIdx.x == 0) {
        float logits[EE];
        #pragma unroll
        for (int e = 0; e < EE; e++) {
            float s = rb[e];
            #pragma unroll
            for (int w = 0; w < 8; w++) s += sh[e][w];
            logits[e] = s;
        }
        int i0 = 0;
        #pragma unroll
        for (int e = 1; e < EE; e++) if (logits[e] > logits[i0]) i0 = e;
        int i1 = -1;
        #pragma unroll
        for (int e = 0; e < EE; e++)
            if (e != i0 && (i1 < 0 || logits[e] > logits[i1])) i1 = e;
        float ex = expf(logits[i1] - logits[i0]);
        float denom = 1.f + ex;
        float p0 = 1.f / denom, p1 = ex / denom;
        int s0 = atomicAdd(&g_expcnt[i0], 1);
        g_expslots[i0 * NTOK + s0] = 2 * t;
        g_gate[2 * t] = p0;
        int s1 = atomicAdd(&g_expcnt[i1], 1);
        g_expslots[i1 * NTOK + s1] = 2 * t + 1;
        g_gate[2 * t + 1] = p1;
    }
}

// ---------------- final combine ---------------------------------------------
__global__ __launch_bounds__(256) void combine_kernel(float* __restrict__ out)
{
    int idx = blockIdx.x * 256 + threadIdx.x;
    int t = idx >> 8;
    int col = idx & 255;
    float g0 = g_gate[2 * t], g1 = g_gate[2 * t + 1];
    float4 hv = ((const float4*)g_h)[idx];
    float4 y0 = ((const float4*)g_ypair)[(size_t)(2 * t) * 256 + col];
    float4 y1 = ((const float4*)g_ypair)[(size_t)(2 * t + 1) * 256 + col];
    float4 o;
    o.x = hv.x + g0 * y0.x + g1 * y1.x;
    o.y = hv.y + g0 * y0.y + g1 * y1.y;
    o.z = hv.z + g0 * y0.z + g1 * y1.z;
    o.w = hv.w + g0 * y0.w + g1 * y1.w;
    ((float4*)out)[idx] = o;
}

// ---------------- launch ----------------------------------------------------
extern "C" void kernel_launch(void* const* d_in, const int* in_sizes, int n_in,
                              void* d_out, int out_size)
{
    const float* q     = (const float*)d_in[0];
    const float* fcos  = (const float*)d_in[3];
    const float* fsin  = (const float*)d_in[4];
    const float* att_w = (const float*)d_in[5];
    const float* ffn_w = (const float*)d_in[6];
    const float* wq    = (const float*)d_in[7];
    const float* wk    = (const float*)d_in[8];
    const float* wv    = (const float*)d_in[9];
    const float* wo    = (const float*)d_in[10];
    const float* rw    = (const float*)d_in[11];
    const float* rb    = (const float*)d_in[12];
    const float* w1    = (const float*)d_in[13];
    const float* w2    = (const float*)d_in[14];
    const float* w3    = (const float*)d_in[15];
    const int*   causal= (const int*)d_in[16];
    float* out = (float*)d_out;

    float *p_xn, *p_qh, *p_kh, *p_vh, *p_att, *p_h, *p_hidden;
    cudaGetSymbolAddress((void**)&p_xn, g_xn);
    cudaGetSymbolAddress((void**)&p_qh, g_qh);
    cudaGetSymbolAddress((void**)&p_kh, g_kh);
    cudaGetSymbolAddress((void**)&p_vh, g_vh);
    cudaGetSymbolAddress((void**)&p_att, g_att);
    cudaGetSymbolAddress((void**)&p_h, g_h);
    cudaGetSymbolAddress((void**)&p_hidden, g_hidden);

    cudaFuncSetAttribute(attn_mma_kernel,
                         cudaFuncAttributeMaxDynamicSharedMemorySize, ATT_SMEM);
    cudaFuncSetAttribute(gemm_mma_proj3,
                         cudaFuncAttributeMaxDynamicSharedMemorySize, PROJ_SMEM);
    cudaFuncSetAttribute(gemm_mma_qkv,
                         cudaFuncAttributeMaxDynamicSharedMemorySize, PROJ_SMEM);
    cudaFuncSetAttribute(gemm_mma_w13,
                         cudaFuncAttributeMaxDynamicSharedMemorySize, W13_SMEM);
    cudaFuncSetAttribute(gemm_mma_w2,
                         cudaFuncAttributeMaxDynamicSharedMemorySize, W2_SMEM);

    // 1. qn = rmsnorm(q) * att_norm_w
    rmsnorm_kernel<<<NTOK, 256>>>(q, att_w, p_xn);

    // 2. fused QKV projection
    gemm_mma_qkv<<<dim3(3 * DD / 128, NTOK / 128), 256, PROJ_SMEM>>>(
        p_xn, wq, wk, wv, p_qh, p_kh, p_vh);

    // 3. RoPE
    rope_kernel<<<(NTOK * HH * (HDD / 2)) / 256, 256>>>(p_qh, p_kh, fcos, fsin);

    // 4. flash attention (tf32 tensor cores)
    attn_mma_kernel<<<dim3(SS / 64, BB * HH), 128, ATT_SMEM>>>(
        p_qh, p_kh, p_vh, p_att, causal);

    // 5. h = q + att @ wo^T
    gemm_mma_proj3<<<dim3(DD / 128, NTOK / 128), 256, PROJ_SMEM>>>(
        p_att, wo, q, p_h, DD, DD);

    // 6. hn = rmsnorm(h)
    rmsnorm_kernel<<<NTOK, 256>>>(p_h, ffn_w, p_xn);

    // 7. routing
    zero_counts_kernel<<<1, 32>>>();
    router_kernel<<<NTOK, 256>>>(p_xn, rw, rb);

    // 8. MoE: fused w1+w3 (3-stage), then w2 (N=64 tiles, 3-stage)
    gemm_mma_w13<<<dim3(FF / 64, NTOK / 128, EE), 256, W13_SMEM>>>(p_xn, w1, w3);
    gemm_mma_w2<<<dim3(DD / 64, NTOK / 128, EE), 256, W2_SMEM>>>(p_hidden, w2);

    // 9. combine
    combine_kernel<<<NTOK, 256>>>(out);
}

// round 9
// speedup vs baseline: 1.4505x; 1.4505x over previous
#include <cuda_runtime.h>
#include <math.h>
#include <stdint.h>

// Problem constants
#define BB 4
#define SS 1024
#define DD 1024
#define HH 16
#define HDD 64
#define EE 8
#define FF 4096
#define NTOK 4096      // B*S
#define NSLOT 8192     // NTOK * K(=2)
#define RMS_EPS 1e-6f
#define ATT_SCALE 0.125f   // 1/sqrt(64)

// ---------------- scratch (static device globals; no runtime allocation) ----
__device__ float g_xn[NTOK * DD];
__device__ float g_qh[NTOK * DD];
__device__ float g_kh[NTOK * DD];
__device__ float g_vh[NTOK * DD];
__device__ float g_att[NTOK * DD];
__device__ float g_h[NTOK * DD];
__device__ float g_hidden[(size_t)NSLOT * FF];
__device__ float g_ypair[(size_t)NSLOT * DD];
__device__ float g_gate[NSLOT];
__device__ int   g_expcnt[EE];
__device__ int   g_expslots[EE * NTOK];

// ---------------- helpers ---------------------------------------------------
__device__ __forceinline__ void mma_tf32(float* c, const uint32_t* a, const uint32_t* b) {
    asm volatile(
        "mma.sync.aligned.m16n8k8.row.col.f32.tf32.tf32.f32 "
        "{%0,%1,%2,%3}, {%4,%5,%6,%7}, {%8,%9}, {%0,%1,%2,%3};\n"
        : "+f"(c[0]), "+f"(c[1]), "+f"(c[2]), "+f"(c[3])
        : "r"(a[0]), "r"(a[1]), "r"(a[2]), "r"(a[3]), "r"(b[0]), "r"(b[1]));
}

__device__ __forceinline__ void cp16(uint32_t dst, const void* src) {
    asm volatile("cp.async.cg.shared.global [%0], [%1], 16;\n"
                 :: "r"(dst), "l"(src));
}
__device__ __forceinline__ void cp16z(uint32_t dst, const void* src, int ok) {
    asm volatile("cp.async.cg.shared.global [%0], [%1], 16, %2;\n"
                 :: "r"(dst), "l"(src), "r"(ok ? 16 : 0));
}
__device__ __forceinline__ void cp_commit() {
    asm volatile("cp.async.commit_group;\n" ::: "memory");
}
template <int N>
__device__ __forceinline__ void cp_wait() {
    asm volatile("cp.async.wait_group %0;\n" :: "n"(N) : "memory");
}

// Smem tiles: 128x32 (A / full-width B) and 64x32 (half-width B), stride 36.
#define TSTR 36
#define TILEW (128 * TSTR)                    // uint32 per 128-row tile
#define TILEB (64 * TSTR)                     // uint32 per 64-row tile
#define PROJ_SMEM  (6 * TILEW * 4)            // S=3 x (A + B128) = 110592 B
#define W13_SMEM   ((2 * TILEW + 4 * TILEB) * 4)  // S=2 x (A + 2xB64) = 73728 B (3 CTAs/SM)
#define W2_STAGE   (TILEW + TILEB)            // u32 per stage (A + B64)
#define W2_SMEM    (2 * W2_STAGE * 4)         // S=2 = 55296 B (4 CTAs/SM)

// ---------------- RMSNorm ---------------------------------------------------
__global__ __launch_bounds__(256) void rmsnorm_kernel(
    const float* __restrict__ x, const float* __restrict__ w,
    float* __restrict__ out)
{
    int t = blockIdx.x;
    const float4* xr = (const float4*)(x + (size_t)t * DD);
    float4 v = xr[threadIdx.x];
    float ss = v.x * v.x + v.y * v.y + v.z * v.z + v.w * v.w;
    #pragma unroll
    for (int o = 16; o; o >>= 1) ss += __shfl_xor_sync(0xffffffffu, ss, o);
    __shared__ float sh[8];
    __shared__ float stot;
    int warp = threadIdx.x >> 5;
    if ((threadIdx.x & 31) == 0) sh[warp] = ss;
    __syncthreads();
    if (threadIdx.x == 0) {
        float s = 0.f;
        #pragma unroll
        for (int i = 0; i < 8; i++) s += sh[i];
        stot = rsqrtf(s / (float)DD + RMS_EPS);
    }
    __syncthreads();
    float sc = stot;
    float4 wv = ((const float4*)w)[threadIdx.x];
    float4 o;
    o.x = v.x * sc * wv.x; o.y = v.y * sc * wv.y;
    o.z = v.z * sc * wv.z; o.w = v.w * sc * wv.w;
    ((float4*)(out + (size_t)t * DD))[threadIdx.x] = o;
}

// ---- 3-stage issue macro for dense proj (A + B 128-row tiles) --------------
#define ISSUE_PROJ(tile, st) do {                                              \
    const int koff_ = (tile) * 32;                                             \
    const uint32_t ao_ = (uint32_t)(st) * TILEW * 4;                           \
    _Pragma("unroll")                                                          \
    for (int i_ = 0; i_ < 4; i_++) {                                           \
        cp16(dA0 + ao_ + i_ * 32 * TSTR * 4, Ap + (size_t)i_ * 32 * Kk + koff_); \
        cp16(dB0 + ao_ + i_ * 32 * TSTR * 4, Wp + (size_t)i_ * 32 * Kk + koff_); \
    }                                                                          \
    cp_commit();                                                               \
} while (0)

// Shared compute step for 128x128 tile (acc[4][4][4])
#define COMPUTE_TILE(Ab, Bb)                                                   \
    _Pragma("unroll")                                                          \
    for (int k8 = 0; k8 < 4; k8++) {                                           \
        int kb = k8 * 8;                                                       \
        uint32_t bf[4][2];                                                     \
        _Pragma("unroll")                                                      \
        for (int ni = 0; ni < 4; ni++) {                                       \
            int n = warpN * 32 + ni * 8 + g;                                   \
            bf[ni][0] = (Bb)[n * TSTR + kb + t];                               \
            bf[ni][1] = (Bb)[n * TSTR + kb + t + 4];                           \
        }                                                                      \
        _Pragma("unroll")                                                      \
        for (int mi = 0; mi < 4; mi++) {                                       \
            int m = warpM * 64 + mi * 16 + g;                                  \
            uint32_t af[4];                                                    \
            af[0] = (Ab)[m * TSTR + kb + t];                                   \
            af[1] = (Ab)[(m + 8) * TSTR + kb + t];                             \
            af[2] = (Ab)[m * TSTR + kb + t + 4];                               \
            af[3] = (Ab)[(m + 8) * TSTR + kb + t + 4];                         \
            _Pragma("unroll")                                                  \
            for (int ni = 0; ni < 4; ni++)                                     \
                mma_tf32(acc[mi][ni], af, bf[ni]);                             \
        }                                                                      \
    }

// ---------------- dense proj GEMM, 3-stage pipeline, 1 barrier/tile ---------
__global__ __launch_bounds__(256) void gemm_mma_proj3(
    const float* __restrict__ A, const float* __restrict__ W,
    const float* __restrict__ resid, float* __restrict__ C,
    int Kk, int Nn)
{
    extern __shared__ uint32_t smbuf[];
    uint32_t* As = smbuf;                  // [3][TILEW]
    uint32_t* Bs = smbuf + 3 * TILEW;      // [3][TILEW]
    const uint32_t smA = (uint32_t)__cvta_generic_to_shared(As);
    const uint32_t smB = (uint32_t)__cvta_generic_to_shared(Bs);

    const int tid = threadIdx.x;
    const int lane = tid & 31, warp = tid >> 5;
    const int warpM = warp >> 2, warpN = warp & 3;
    const int g = lane >> 2, t = lane & 3;
    const int m0 = blockIdx.y * 128, n0 = blockIdx.x * 128;
    float acc[4][4][4] = {};

    const int lrow = tid >> 3;
    const int lkf = (tid & 7) * 4;
    const float* Ap = A + (size_t)(m0 + lrow) * Kk + lkf;
    const float* Wp = W + (size_t)(n0 + lrow) * Kk + lkf;
    const uint32_t dA0 = smA + (lrow * TSTR + lkf) * 4;
    const uint32_t dB0 = smB + (lrow * TSTR + lkf) * 4;

    const int nt = Kk >> 5;
    ISSUE_PROJ(0, 0);
    ISSUE_PROJ(1, 1);

    for (int kt = 0; kt < nt; kt++) {
        if (kt + 1 < nt) cp_wait<1>(); else cp_wait<0>();
        __syncthreads();
        if (kt + 2 < nt) {
            ISSUE_PROJ(kt + 2, (kt + 2) % 3);
        }
        const uint32_t* Ab = As + (kt % 3) * TILEW;
        const uint32_t* Bb = Bs + (kt % 3) * TILEW;
        COMPUTE_TILE(Ab, Bb);
    }

    #pragma unroll
    for (int mi = 0; mi < 4; mi++) {
        int r0 = m0 + warpM * 64 + mi * 16 + g;
        #pragma unroll
        for (int ni = 0; ni < 4; ni++) {
            int c = n0 + warpN * 32 + ni * 8 + 2 * t;
            size_t i0 = (size_t)r0 * Nn + c;
            size_t i1 = i0 + (size_t)8 * Nn;
            float2 v0 = make_float2(acc[mi][ni][0], acc[mi][ni][1]);
            float2 v1 = make_float2(acc[mi][ni][2], acc[mi][ni][3]);
            if (resid) {
                float2 r = *(const float2*)(resid + i0); v0.x += r.x; v0.y += r.y;
                r = *(const float2*)(resid + i1); v1.x += r.x; v1.y += r.y;
            }
            *(float2*)(C + i0) = v0;
            *(float2*)(C + i1) = v1;
        }
    }
}

// ---------------- fused QKV projection --------------------------------------
__global__ __launch_bounds__(256) void gemm_mma_qkv(
    const float* __restrict__ A,
    const float* __restrict__ wq, const float* __restrict__ wk,
    const float* __restrict__ wv,
    float* __restrict__ qo, float* __restrict__ ko, float* __restrict__ vo)
{
    extern __shared__ uint32_t smbuf[];
    uint32_t* As = smbuf;
    uint32_t* Bs = smbuf + 3 * TILEW;
    const uint32_t smA = (uint32_t)__cvta_generic_to_shared(As);
    const uint32_t smB = (uint32_t)__cvta_generic_to_shared(Bs);

    const int tid = threadIdx.x;
    const int lane = tid & 31, warp = tid >> 5;
    const int warpM = warp >> 2, warpN = warp & 3;
    const int g = lane >> 2, t = lane & 3;
    const int m0 = blockIdx.y * 128;
    const int n0t = blockIdx.x * 128;

    const float* W; float* C; int n0;
    if (n0t < DD)            { W = wq; C = qo; n0 = n0t; }
    else if (n0t < 2 * DD)   { W = wk; C = ko; n0 = n0t - DD; }
    else                     { W = wv; C = vo; n0 = n0t - 2 * DD; }

    const int Kk = DD;
    float acc[4][4][4] = {};

    const int lrow = tid >> 3;
    const int lkf = (tid & 7) * 4;
    const float* Ap = A + (size_t)(m0 + lrow) * Kk + lkf;
    const float* Wp = W + (size_t)(n0 + lrow) * Kk + lkf;
    const uint32_t dA0 = smA + (lrow * TSTR + lkf) * 4;
    const uint32_t dB0 = smB + (lrow * TSTR + lkf) * 4;

    const int nt = Kk >> 5;
    ISSUE_PROJ(0, 0);
    ISSUE_PROJ(1, 1);

    for (int kt = 0; kt < nt; kt++) {
        if (kt + 1 < nt) cp_wait<1>(); else cp_wait<0>();
        __syncthreads();
        if (kt + 2 < nt) {
            ISSUE_PROJ(kt + 2, (kt + 2) % 3);
        }
        const uint32_t* Ab = As + (kt % 3) * TILEW;
        const uint32_t* Bb = Bs + (kt % 3) * TILEW;
        COMPUTE_TILE(Ab, Bb);
    }

    #pragma unroll
    for (int mi = 0; mi < 4; mi++) {
        int r0 = m0 + warpM * 64 + mi * 16 + g;
        #pragma unroll
        for (int ni = 0; ni < 4; ni++) {
            int c = n0 + warpN * 32 + ni * 8 + 2 * t;
            size_t i0 = (size_t)r0 * DD + c;
            size_t i1 = i0 + (size_t)8 * DD;
            *(float2*)(C + i0) = make_float2(acc[mi][ni][0], acc[mi][ni][1]);
            *(float2*)(C + i1) = make_float2(acc[mi][ni][2], acc[mi][ni][3]);
        }
    }
}

// ---------------- fused w1+w3 expert GEMM (R6 version: 2-stage, 3 CTAs/SM) --
// hidden[slot, n] = silu(A@w1^T) * (A@w3^T), both computed in one CTA.
// grid (FF/64, NTOK/128, E), block 256. Warp grid 2(M) x 4(N): 64x16 per B.
__global__ __launch_bounds__(256) void gemm_mma_w13(
    const float* __restrict__ A,
    const float* __restrict__ W1base, const float* __restrict__ W3base)
{
    const int e = blockIdx.z;
    const int count = g_expcnt[e];
    const int m0 = blockIdx.y * 128;
    if (m0 >= count) return;

    extern __shared__ uint32_t smbuf[];
    uint32_t* As  = smbuf;                          // [2][TILEW]
    uint32_t* B1s = smbuf + 2 * TILEW;              // [2][TILEB]
    uint32_t* B3s = smbuf + 2 * TILEW + 2 * TILEB;  // [2][TILEB]
    __shared__ int srow[128];
    const uint32_t smA  = (uint32_t)__cvta_generic_to_shared(As);
    const uint32_t smB1 = (uint32_t)__cvta_generic_to_shared(B1s);
    const uint32_t smB3 = (uint32_t)__cvta_generic_to_shared(B3s);

    const int tid = threadIdx.x;
    if (tid < 128) {
        int r = m0 + tid;
        srow[tid] = (r < count) ? g_expslots[e * NTOK + r] : -1;
    }
    __syncthreads();

    const int lane = tid & 31, warp = tid >> 5;
    const int warpM = warp >> 2, warpN = warp & 3;
    const int g = lane >> 2, t = lane & 3;
    const int n0 = blockIdx.x * 64;
    const float* W1 = W1base + (size_t)e * FF * DD;
    const float* W3 = W3base + (size_t)e * FF * DD;
    float acc1[4][2][4] = {};
    float acc3[4][2][4] = {};

    const int lrow = tid >> 3;
    const int lkf = (tid & 7) * 4;

    const float* arp[4];
    int aok[4];
    #pragma unroll
    for (int i = 0; i < 4; i++) {
        int s = srow[lrow + i * 32];
        aok[i] = (s >= 0);
        int arow = (s >= 0) ? (s >> 1) : 0;
        arp[i] = A + (size_t)arow * DD + lkf;
    }
    const float* Wp1 = W1 + (size_t)(n0 + lrow) * DD + lkf;
    const float* Wp3 = W3 + (size_t)(n0 + lrow) * DD + lkf;
    const uint32_t dA0  = smA  + (lrow * TSTR + lkf) * 4;
    const uint32_t dB10 = smB1 + (lrow * TSTR + lkf) * 4;
    const uint32_t dB30 = smB3 + (lrow * TSTR + lkf) * 4;

    const int nt = DD >> 5;
    #pragma unroll
    for (int i = 0; i < 4; i++)
        cp16z(dA0 + i * 32 * TSTR * 4, arp[i], aok[i]);
    #pragma unroll
    for (int i = 0; i < 2; i++) {
        cp16(dB10 + i * 32 * TSTR * 4, Wp1 + (size_t)i * 32 * DD);
        cp16(dB30 + i * 32 * TSTR * 4, Wp3 + (size_t)i * 32 * DD);
    }
    cp_commit();

    for (int kt = 0; kt < nt; kt++) {
        const int buf = kt & 1;
        if (kt + 1 < nt) {
            const int koff = (kt + 1) * 32;
            const uint32_t aoW = (uint32_t)(buf ^ 1) * TILEW * 4;
            const uint32_t aoB = (uint32_t)(buf ^ 1) * TILEB * 4;
            #pragma unroll
            for (int i = 0; i < 4; i++)
                cp16z(dA0 + aoW + i * 32 * TSTR * 4, arp[i] + koff, aok[i]);
            #pragma unroll
            for (int i = 0; i < 2; i++) {
                cp16(dB10 + aoB + i * 32 * TSTR * 4, Wp1 + (size_t)i * 32 * DD + koff);
                cp16(dB30 + aoB + i * 32 * TSTR * 4, Wp3 + (size_t)i * 32 * DD + koff);
            }
            cp_commit();
            cp_wait<1>();
        } else {
            cp_wait<0>();
        }
        __syncthreads();

        const uint32_t* Ab  = As  + buf * TILEW;
        const uint32_t* B1b = B1s + buf * TILEB;
        const uint32_t* B3b = B3s + buf * TILEB;
        #pragma unroll
        for (int k8 = 0; k8 < 4; k8++) {
            int kb = k8 * 8;
            uint32_t bf1[2][2], bf3[2][2];
            #pragma unroll
            for (int ni = 0; ni < 2; ni++) {
                int n = warpN * 16 + ni * 8 + g;
                bf1[ni][0] = B1b[n * TSTR + kb + t];
                bf1[ni][1] = B1b[n * TSTR + kb + t + 4];
                bf3[ni][0] = B3b[n * TSTR + kb + t];
                bf3[ni][1] = B3b[n * TSTR + kb + t + 4];
            }
            #pragma unroll
            for (int mi = 0; mi < 4; mi++) {
                int m = warpM * 64 + mi * 16 + g;
                uint32_t af[4];
                af[0] = Ab[m * TSTR + kb + t];
                af[1] = Ab[(m + 8) * TSTR + kb + t];
                af[2] = Ab[m * TSTR + kb + t + 4];
                af[3] = Ab[(m + 8) * TSTR + kb + t + 4];
                #pragma unroll
                for (int ni = 0; ni < 2; ni++) {
                    mma_tf32(acc1[mi][ni], af, bf1[ni]);
                    mma_tf32(acc3[mi][ni], af, bf3[ni]);
                }
            }
        }
        __syncthreads();
    }

    #pragma unroll
    for (int mi = 0; mi < 4; mi++) {
        int mloc0 = warpM * 64 + mi * 16 + g;
        #pragma unroll
        for (int half = 0; half < 2; half++) {
            int mloc = mloc0 + half * 8;
            int s = srow[mloc];
            if (s < 0) continue;
            #pragma unroll
            for (int ni = 0; ni < 2; ni++) {
                int c = n0 + warpN * 16 + ni * 8 + 2 * t;
                float h1x = acc1[mi][ni][half * 2],     h1y = acc1[mi][ni][half * 2 + 1];
                float h3x = acc3[mi][ni][half * 2],     h3y = acc3[mi][ni][half * 2 + 1];
                float2 o;
                o.x = (h1x / (1.f + expf(-h1x))) * h3x;
                o.y = (h1y / (1.f + expf(-h1y))) * h3y;
                *(float2*)(&g_hidden[(size_t)s * FF + c]) = o;
            }
        }
    }
}

// ---------------- w2 expert GEMM (N=64 tiles, 2-stage, 4 CTAs/SM) -----------
// g_ypair[slot] = hidden[slot] @ w2^T. grid (DD/64, NTOK/128, E), block 256.
__global__ __launch_bounds__(256) void gemm_mma_w2(
    const float* __restrict__ A, const float* __restrict__ Wbase)
{
    const int e = blockIdx.z;
    const int count = g_expcnt[e];
    const int m0 = blockIdx.y * 128;
    if (m0 >= count) return;

    extern __shared__ uint32_t smbuf[];     // [2][W2_STAGE]
    __shared__ int srow[128];
    const uint32_t smBase = (uint32_t)__cvta_generic_to_shared(smbuf);

    const int tid = threadIdx.x;
    if (tid < 128) {
        int r = m0 + tid;
        srow[tid] = (r < count) ? g_expslots[e * NTOK + r] : -1;
    }
    __syncthreads();

    const int lane = tid & 31, warp = tid >> 5;
    const int warpM = warp >> 2, warpN = warp & 3;
    const int g = lane >> 2, t = lane & 3;
    const int n0 = blockIdx.x * 64;
    const float* W = Wbase + (size_t)e * DD * FF;
    float acc[4][2][4] = {};

    const int lrow = tid >> 3;
    const int lkf = (tid & 7) * 4;

    const float* arp[4];
    int aok[4];
    #pragma unroll
    for (int i = 0; i < 4; i++) {
        int s = srow[lrow + i * 32];
        aok[i] = (s >= 0);
        int arow = (s >= 0) ? s : 0;
        arp[i] = A + (size_t)arow * FF + lkf;
    }
    const float* Wp = W + (size_t)(n0 + lrow) * FF + lkf;
    const uint32_t dA0 = smBase + (lrow * TSTR + lkf) * 4;
    const uint32_t dB0 = smBase + (TILEW + lrow * TSTR + lkf) * 4;

    const int nt = FF >> 5;    // 128
    #pragma unroll
    for (int i = 0; i < 4; i++)
        cp16z(dA0 + i * 32 * TSTR * 4, arp[i], aok[i]);
    #pragma unroll
    for (int i = 0; i < 2; i++)
        cp16(dB0 + i * 32 * TSTR * 4, Wp + (size_t)i * 32 * FF);
    cp_commit();

    for (int kt = 0; kt < nt; kt++) {
        const int buf = kt & 1;
        if (kt + 1 < nt) {
            const int koff = (kt + 1) * 32;
            const uint32_t bo = (uint32_t)(buf ^ 1) * W2_STAGE * 4;
            #pragma unroll
            for (int i = 0; i < 4; i++)
                cp16z(dA0 + bo + i * 32 * TSTR * 4, arp[i] + koff, aok[i]);
            #pragma unroll
            for (int i = 0; i < 2; i++)
                cp16(dB0 + bo + i * 32 * TSTR * 4, Wp + (size_t)i * 32 * FF + koff);
            cp_commit();
            cp_wait<1>();
        } else {
            cp_wait<0>();
        }
        __syncthreads();

        const uint32_t* Sb = smbuf + buf * W2_STAGE;
        const uint32_t* Ab = Sb;
        const uint32_t* Bb = Sb + TILEW;
        #pragma unroll
        for (int k8 = 0; k8 < 4; k8++) {
            int kb = k8 * 8;
            uint32_t bf[2][2];
            #pragma unroll
            for (int ni = 0; ni < 2; ni++) {
                int n = warpN * 16 + ni * 8 + g;
                bf[ni][0] = Bb[n * TSTR + kb + t];
                bf[ni][1] = Bb[n * TSTR + kb + t + 4];
            }
            #pragma unroll
            for (int mi = 0; mi < 4; mi++) {
                int m = warpM * 64 + mi * 16 + g;
                uint32_t af[4];
                af[0] = Ab[m * TSTR + kb + t];
                af[1] = Ab[(m + 8) * TSTR + kb + t];
                af[2] = Ab[m * TSTR + kb + t + 4];
                af[3] = Ab[(m + 8) * TSTR + kb + t + 4];
                #pragma unroll
                for (int ni = 0; ni < 2; ni++)
                    mma_tf32(acc[mi][ni], af, bf[ni]);
            }
        }
        __syncthreads();
    }

    #pragma unroll
    for (int mi = 0; mi < 4; mi++) {
        int mloc0 = warpM * 64 + mi * 16 + g;
        #pragma unroll
        for (int half = 0; half < 2; half++) {
            int mloc = mloc0 + half * 8;
            int s = srow[mloc];
            if (s < 0) continue;
            #pragma unroll
            for (int ni = 0; ni < 2; ni++) {
                int c = n0 + warpN * 16 + ni * 8 + 2 * t;
                *(float2*)(&g_ypair[(size_t)s * DD + c]) =
                    make_float2(acc[mi][ni][half * 2], acc[mi][ni][half * 2 + 1]);
            }
        }
    }
}

// ---------------- RoPE (q and k in place) -----------------------------------
__global__ void rope_kernel(float* __restrict__ qh, float* __restrict__ kh,
                            const float* __restrict__ cosb,
                            const float* __restrict__ sinb)
{
    int idx = blockIdx.x * blockDim.x + threadIdx.x;
    int i = idx & 31;
    int th = idx >> 5;
    int t = th >> 4;
    int s = t & (SS - 1);
    float c = cosb[s * 32 + i], sn = sinb[s * 32 + i];
    size_t base = (size_t)th * HDD + i * 2;
    float xr = qh[base], xi = qh[base + 1];
    qh[base]     = xr * c - xi * sn;
    qh[base + 1] = xr * sn + xi * c;
    xr = kh[base]; xi = kh[base + 1];
    kh[base]     = xr * c - xi * sn;
    kh[base + 1] = xr * sn + xi * c;
}

// ---------------- Flash attention (tf32 tensor cores) -----------------------
#define ASTR 68
#define ATT_SMEM (4 * 64 * ASTR * 4)
__global__ __launch_bounds__(128) void attn_mma_kernel(
    const float* __restrict__ Q, const float* __restrict__ K,
    const float* __restrict__ V, float* __restrict__ O,
    const int* __restrict__ causal_flag)
{
    extern __shared__ float sm[];
    float* Qs = sm;
    float* Ks = Qs + 64 * ASTR;
    float* Vt = Ks + 64 * ASTR;   // transposed: Vt[d][kpos]
    float* Ps = Vt + 64 * ASTR;
    const int qt = blockIdx.x, bh = blockIdx.y;
    const int b = bh >> 4, h = bh & 15;
    const int tid = threadIdx.x;
    const int warp = tid >> 5, lane = tid & 31;
    const int g = lane >> 2, t = lane & 3;
    const int causal = *causal_flag;
    const size_t base = (size_t)b * SS * DD + (size_t)h * HDD;
    const float* Qb = Q + base;
    const float* Kb = K + base;
    const float* Vb = V + base;
    const int q0 = qt * 64;

    {
        int row = tid >> 1;
        int cb = (tid & 1) * 32;
        const float* src = Qb + (size_t)(q0 + row) * DD + cb;
        #pragma unroll
        for (int j = 0; j < 8; j++) {
            float4 v = *(const float4*)(src + j * 4);
            float* d = &Qs[row * ASTR + cb + j * 4];
            d[0] = v.x * ATT_SCALE; d[1] = v.y * ATT_SCALE;
            d[2] = v.z * ATT_SCALE; d[3] = v.w * ATT_SCALE;
        }
    }

    float m_run0 = -1e30f, m_run1 = -1e30f;
    float l_run0 = 0.f, l_run1 = 0.f;
    float Oacc[8][4] = {};
    const int mrow = warp * 16 + g;

    const int ktmax = causal ? qt : (SS / 64 - 1);
    for (int kt = 0; kt <= ktmax; kt++) {
        __syncthreads();
        {
            int row = tid >> 1;
            int cb = (tid & 1) * 32;
            const float* ksrc = Kb + (size_t)(kt * 64 + row) * DD + cb;
            const float* vsrc = Vb + (size_t)(kt * 64 + row) * DD + cb;
            #pragma unroll
            for (int j = 0; j < 8; j++) {
                float4 kv = *(const float4*)(ksrc + j * 4);
                float* d = &Ks[row * ASTR + cb + j * 4];
                d[0] = kv.x; d[1] = kv.y; d[2] = kv.z; d[3] = kv.w;
                float4 vv = *(const float4*)(vsrc + j * 4);
                int c = cb + j * 4;
                Vt[(c + 0) * ASTR + row] = vv.x;
                Vt[(c + 1) * ASTR + row] = vv.y;
                Vt[(c + 2) * ASTR + row] = vv.z;
                Vt[(c + 3) * ASTR + row] = vv.w;
            }
        }
        __syncthreads();

        float sacc[8][4] = {};
        const uint32_t* Qsu = (const uint32_t*)Qs;
        const uint32_t* Ksu = (const uint32_t*)Ks;
        #pragma unroll
        for (int k8 = 0; k8 < 8; k8++) {
            int kb = k8 * 8;
            uint32_t af[4];
            af[0] = Qsu[mrow * ASTR + kb + t];
            af[1] = Qsu[(mrow + 8) * ASTR + kb + t];
            af[2] = Qsu[mrow * ASTR + kb + t + 4];
            af[3] = Qsu[(mrow + 8) * ASTR + kb + t + 4];
            #pragma unroll
            for (int ni = 0; ni < 8; ni++) {
                uint32_t bf[2];
                bf[0] = Ksu[(ni * 8 + g) * ASTR + kb + t];
                bf[1] = Ksu[(ni * 8 + g) * ASTR + kb + t + 4];
                mma_tf32(sacc[ni], af, bf);
            }
        }

        const int row0 = q0 + mrow, row1 = row0 + 8;
        if (causal && kt == qt) {
            #pragma unroll
            for (int ni = 0; ni < 8; ni++) {
                int c0 = kt * 64 + ni * 8 + 2 * t;
                if (c0     > row0) sacc[ni][0] = -1e30f;
                if (c0 + 1 > row0) sacc[ni][1] = -1e30f;
                if (c0     > row1) sacc[ni][2] = -1e30f;
                if (c0 + 1 > row1) sacc[ni][3] = -1e30f;
            }
        }

        float ml0 = -1e30f, ml1 = -1e30f;
        #pragma unroll
        for (int ni = 0; ni < 8; ni++) {
            ml0 = fmaxf(ml0, fmaxf(sacc[ni][0], sacc[ni][1]));
            ml1 = fmaxf(ml1, fmaxf(sacc[ni][2], sacc[ni][3]));
        }
        ml0 = fmaxf(ml0, __shfl_xor_sync(0xffffffffu, ml0, 1));
        ml0 = fmaxf(ml0, __shfl_xor_sync(0xffffffffu, ml0, 2));
        ml1 = fmaxf(ml1, __shfl_xor_sync(0xffffffffu, ml1, 1));
        ml1 = fmaxf(ml1, __shfl_xor_sync(0xffffffffu, ml1, 2));
        float mn0 = fmaxf(m_run0, ml0), mn1 = fmaxf(m_run1, ml1);
        float a0 = expf(m_run0 - mn0), a1 = expf(m_run1 - mn1);
        float ps0 = 0.f, ps1 = 0.f;
        #pragma unroll
        for (int ni = 0; ni < 8; ni++) {
            float p0 = expf(sacc[ni][0] - mn0);
            float p1 = expf(sacc[ni][1] - mn0);
            float p2 = expf(sacc[ni][2] - mn1);
            float p3 = expf(sacc[ni][3] - mn1);
            ps0 += p0 + p1; ps1 += p2 + p3;
            int cl = ni * 8 + 2 * t;
            *(float2*)&Ps[mrow * ASTR + cl]       = make_float2(p0, p1);
            *(float2*)&Ps[(mrow + 8) * ASTR + cl] = make_float2(p2, p3);
        }
        ps0 += __shfl_xor_sync(0xffffffffu, ps0, 1);
        ps0 += __shfl_xor_sync(0xffffffffu, ps0, 2);
        ps1 += __shfl_xor_sync(0xffffffffu, ps1, 1);
        ps1 += __shfl_xor_sync(0xffffffffu, ps1, 2);
        l_run0 = l_run0 * a0 + ps0;
        l_run1 = l_run1 * a1 + ps1;
        m_run0 = mn0; m_run1 = mn1;
        #pragma unroll
        for (int ni = 0; ni < 8; ni++) {
            Oacc[ni][0] *= a0; Oacc[ni][1] *= a0;
            Oacc[ni][2] *= a1; Oacc[ni][3] *= a1;
        }
        __syncwarp();

        const uint32_t* Psu = (const uint32_t*)Ps;
        const uint32_t* Vtu = (const uint32_t*)Vt;
        #pragma unroll
        for (int k8 = 0; k8 < 8; k8++) {
            int kb = k8 * 8;
            uint32_t af[4];
            af[0] = Psu[mrow * ASTR + kb + t];
            af[1] = Psu[(mrow + 8) * ASTR + kb + t];
            af[2] = Psu[mrow * ASTR + kb + t + 4];
            af[3] = Psu[(mrow + 8) * ASTR + kb + t + 4];
            #pragma unroll
            for (int ni = 0; ni < 8; ni++) {
                uint32_t bf[2];
                bf[0] = Vtu[(ni * 8 + g) * ASTR + kb + t];
                bf[1] = Vtu[(ni * 8 + g) * ASTR + kb + t + 4];
                mma_tf32(Oacc[ni], af, bf);
            }
        }
    }

    float i0 = 1.f / l_run0, i1 = 1.f / l_run1;
    const int row0 = q0 + mrow;
    float* dst0 = O + (size_t)(b * SS + row0) * DD + (size_t)h * HDD;
    float* dst1 = dst0 + (size_t)8 * DD;
    #pragma unroll
    for (int ni = 0; ni < 8; ni++) {
        int d = ni * 8 + 2 * t;
        *(float2*)(dst0 + d) = make_float2(Oacc[ni][0] * i0, Oacc[ni][1] * i0);
        *(float2*)(dst1 + d) = make_float2(Oacc[ni][2] * i1, Oacc[ni][3] * i1);
    }
}

// ---------------- router + top-2 --------------------------------------------
__global__ void zero_counts_kernel()
{
    if (threadIdx.x < EE) g_expcnt[threadIdx.x] = 0;
}

__global__ __launch_bounds__(256) void router_kernel(
    const float* __restrict__ xn, const float* __restrict__ rw,
    const float* __restrict__ rb)
{
    int t = blockIdx.x;
    float4 xv = ((const float4*)(xn + (size_t)t * DD))[threadIdx.x];
    float lg[EE];
    #pragma unroll
    for (int e = 0; e < EE; e++) {
        float4 wv = ((const float4*)(rw + (size_t)e * DD))[threadIdx.x];
        lg[e] = xv.x * wv.x + xv.y * wv.y + xv.z * wv.z + xv.w * wv.w;
    }
    #pragma unroll
    for (int o = 16; o; o >>= 1)
        #pragma unroll
        for (int e = 0; e < EE; e++)
            lg[e] += __shfl_xor_sync(0xffffffffu, lg[e], o);
    __shared__ float sh[EE][8];
    int warp = threadIdx.x >> 5;
    if ((threadIdx.x & 31) == 0)
        #pragma unroll
        for (int e = 0; e < EE; e++) sh[e][warp] = lg[e];
    __syncthreads();
    if (threadIdx.x == 0) {
        float logits[EE];
        #pragma unroll
        for (int e = 0; e < EE; e++) {
            float s = rb[e];
            #pragma unroll
            for (int w = 0; w < 8; w++) s += sh[e][w];
            logits[e] = s;
        }
        int i0 = 0;
        #pragma unroll
        for (int e = 1; e < EE; e++) if (logits[e] > logits[i0]) i0 = e;
        int i1 = -1;
        #pragma unroll
        for (int e = 0; e < EE; e++)
            if (e != i0 && (i1 < 0 || logits[e] > logits[i1])) i1 = e;
        float ex = expf(logits[i1] - logits[i0]);
        float denom = 1.f + ex;
        float p0 = 1.f / denom, p1 = ex / denom;
        int s0 = atomicAdd(&g_expcnt[i0], 1);
        g_expslots[i0 * NTOK + s0] = 2 * t;
        g_gate[2 * t] = p0;
        int s1 = atomicAdd(&g_expcnt[i1], 1);
        g_expslots[i1 * NTOK + s1] = 2 * t + 1;
        g_gate[2 * t + 1] = p1;
    }
}

// ---------------- final combine ---------------------------------------------
__global__ __launch_bounds__(256) void combine_kernel(float* __restrict__ out)
{
    int idx = blockIdx.x * 256 + threadIdx.x;
    int t = idx >> 8;
    int col = idx & 255;
    float g0 = g_gate[2 * t], g1 = g_gate[2 * t + 1];
    float4 hv = ((const float4*)g_h)[idx];
    float4 y0 = ((const float4*)g_ypair)[(size_t)(2 * t) * 256 + col];
    float4 y1 = ((const float4*)g_ypair)[(size_t)(2 * t + 1) * 256 + col];
    float4 o;
    o.x = hv.x + g0 * y0.x + g1 * y1.x;
    o.y = hv.y + g0 * y0.y + g1 * y1.y;
    o.z = hv.z + g0 * y0.z + g1 * y1.z;
    o.w = hv.w + g0 * y0.w + g1 * y1.w;
    ((float4*)out)[idx] = o;
}

// ---------------- launch ----------------------------------------------------
extern "C" void kernel_launch(void* const* d_in, const int* in_sizes, int n_in,
                              void* d_out, int out_size)
{
    const float* q     = (const float*)d_in[0];
    const float* fcos  = (const float*)d_in[3];
    const float* fsin  = (const float*)d_in[4];
    const float* att_w = (const float*)d_in[5];
    const float* ffn_w = (const float*)d_in[6];
    const float* wq    = (const float*)d_in[7];
    const float* wk    = (const float*)d_in[8];
    const float* wv    = (const float*)d_in[9];
    const float* wo    = (const float*)d_in[10];
    const float* rw    = (const float*)d_in[11];
    const float* rb    = (const float*)d_in[12];
    const float* w1    = (const float*)d_in[13];
    const float* w2    = (const float*)d_in[14];
    const float* w3    = (const float*)d_in[15];
    const int*   causal= (const int*)d_in[16];
    float* out = (float*)d_out;

    float *p_xn, *p_qh, *p_kh, *p_vh, *p_att, *p_h, *p_hidden;
    cudaGetSymbolAddress((void**)&p_xn, g_xn);
    cudaGetSymbolAddress((void**)&p_qh, g_qh);
    cudaGetSymbolAddress((void**)&p_kh, g_kh);
    cudaGetSymbolAddress((void**)&p_vh, g_vh);
    cudaGetSymbolAddress((void**)&p_att, g_att);
    cudaGetSymbolAddress((void**)&p_h, g_h);
    cudaGetSymbolAddress((void**)&p_hidden, g_hidden);

    cudaFuncSetAttribute(attn_mma_kernel,
                         cudaFuncAttributeMaxDynamicSharedMemorySize, ATT_SMEM);
    cudaFuncSetAttribute(gemm_mma_proj3,
                         cudaFuncAttributeMaxDynamicSharedMemorySize, PROJ_SMEM);
    cudaFuncSetAttribute(gemm_mma_qkv,
                         cudaFuncAttributeMaxDynamicSharedMemorySize, PROJ_SMEM);
    cudaFuncSetAttribute(gemm_mma_w13,
                         cudaFuncAttributeMaxDynamicSharedMemorySize, W13_SMEM);
    cudaFuncSetAttribute(gemm_mma_w2,
                         cudaFuncAttributeMaxDynamicSharedMemorySize, W2_SMEM);

    // 1. qn = rmsnorm(q) * att_norm_w
    rmsnorm_kernel<<<NTOK, 256>>>(q, att_w, p_xn);

    // 2. fused QKV projection
    gemm_mma_qkv<<<dim3(3 * DD / 128, NTOK / 128), 256, PROJ_SMEM>>>(
        p_xn, wq, wk, wv, p_qh, p_kh, p_vh);

    // 3. RoPE
    rope_kernel<<<(NTOK * HH * (HDD / 2)) / 256, 256>>>(p_qh, p_kh, fcos, fsin);

    // 4. flash attention (tf32 tensor cores)
    attn_mma_kernel<<<dim3(SS / 64, BB * HH), 128, ATT_SMEM>>>(
        p_qh, p_kh, p_vh, p_att, causal);

    // 5. h = q + att @ wo^T
    gemm_mma_proj3<<<dim3(DD / 128, NTOK / 128), 256, PROJ_SMEM>>>(
        p_att, wo, q, p_h, DD, DD);

    // 6. hn = rmsnorm(h)
    rmsnorm_kernel<<<NTOK, 256>>>(p_h, ffn_w, p_xn);

    // 7. routing
    zero_counts_kernel<<<1, 32>>>();
    router_kernel<<<NTOK, 256>>>(p_xn, rw, rb);

    // 8. MoE: fused w1+w3 (R6 2-stage, 3 CTAs/SM), then w2 (N=64, 2-stage, 4 CTAs/SM)
    gemm_mma_w13<<<dim3(FF / 64, NTOK / 128, EE), 256, W13_SMEM>>>(p_xn, w1, w3);
    gemm_mma_w2<<<dim3(DD / 64, NTOK / 128, EE), 256, W2_SMEM>>>(p_hidden, w2);

    // 9. combine
    combine_kernel<<<NTOK, 256>>>(out);
}

// round 11
// speedup vs baseline: 1.9831x; 1.3672x over previous
#include <cuda_runtime.h>
#include <cuda_fp16.h>
#include <math.h>
#include <stdint.h>

// Problem constants
#define BB 4
#define SS 1024
#define DD 1024
#define HH 16
#define HDD 64
#define EE 8
#define FF 4096
#define NTOK 4096      // B*S
#define NSLOT 8192     // NTOK * K(=2)
#define RMS_EPS 1e-6f
#define ATT_SCALE 0.125f   // 1/sqrt(64)

// ---------------- scratch (static device globals; no runtime allocation) ----
__device__ float g_xn[NTOK * DD];
__device__ float g_qh[NTOK * DD];
__device__ float g_kh[NTOK * DD];
__device__ float g_vh[NTOK * DD];
__device__ float g_att[NTOK * DD];
__device__ float g_h[NTOK * DD];
__device__ float g_ypair[(size_t)NSLOT * DD];
__device__ float g_gate[NSLOT];
__device__ int   g_expcnt[EE];
__device__ int   g_expslots[EE * NTOK];
// fp16 operands for the MoE GEMMs
__device__ __half g_w1h[(size_t)EE * FF * DD];
__device__ __half g_w3h[(size_t)EE * FF * DD];
__device__ __half g_w2h[(size_t)EE * DD * FF];
__device__ __half g_xnh[NTOK * DD];
__device__ __half g_hidh[(size_t)NSLOT * FF];

// ---------------- helpers ---------------------------------------------------
__device__ __forceinline__ void mma_tf32(float* c, const uint32_t* a, const uint32_t* b) {
    asm volatile(
        "mma.sync.aligned.m16n8k8.row.col.f32.tf32.tf32.f32 "
        "{%0,%1,%2,%3}, {%4,%5,%6,%7}, {%8,%9}, {%0,%1,%2,%3};\n"
        : "+f"(c[0]), "+f"(c[1]), "+f"(c[2]), "+f"(c[3])
        : "r"(a[0]), "r"(a[1]), "r"(a[2]), "r"(a[3]), "r"(b[0]), "r"(b[1]));
}
__device__ __forceinline__ void mma_f16(float* c, const uint32_t* a, const uint32_t* b) {
    asm volatile(
        "mma.sync.aligned.m16n8k16.row.col.f32.f16.f16.f32 "
        "{%0,%1,%2,%3}, {%4,%5,%6,%7}, {%8,%9}, {%0,%1,%2,%3};\n"
        : "+f"(c[0]), "+f"(c[1]), "+f"(c[2]), "+f"(c[3])
        : "r"(a[0]), "r"(a[1]), "r"(a[2]), "r"(a[3]), "r"(b[0]), "r"(b[1]));
}

__device__ __forceinline__ void cp16(uint32_t dst, const void* src) {
    asm volatile("cp.async.cg.shared.global [%0], [%1], 16;\n"
                 :: "r"(dst), "l"(src));
}
__device__ __forceinline__ void cp16z(uint32_t dst, const void* src, int ok) {
    asm volatile("cp.async.cg.shared.global [%0], [%1], 16, %2;\n"
                 :: "r"(dst), "l"(src), "r"(ok ? 16 : 0));
}
__device__ __forceinline__ void cp_commit() {
    asm volatile("cp.async.commit_group;\n" ::: "memory");
}
template <int N>
__device__ __forceinline__ void cp_wait() {
    asm volatile("cp.async.wait_group %0;\n" :: "n"(N) : "memory");
}

// ---- fp32/tf32 smem tiles (proj kernels) -----------------------------------
#define TSTR 36
#define TILEW (128 * TSTR)                    // uint32 per 128-row tile
#define PROJ_SMEM  (6 * TILEW * 4)            // S=3 x (A + B128) = 110592 B

// ---- fp16 smem tiles (MoE kernels): 32-k row = 16 words, stride 20 words ---
#define HSTR 20
#define HA_TILE (128 * HSTR)                  // 2560 words
#define HB_TILE (64 * HSTR)                   // 1280 words
#define W13H_STAGE (HA_TILE + 2 * HB_TILE)    // 5120 words = 20480 B
#define W13H_SMEM  (2 * W13H_STAGE * 4)       // 40960 B
#define W2H_STAGE  (2 * HA_TILE)              // A(128) + B(128) = 5120 words
#define W2H_SMEM   (2 * W2H_STAGE * 4)        // 40960 B

// ---------------- fp32 -> fp16 conversion (weights) -------------------------
__global__ __launch_bounds__(256) void cvt_h_kernel(
    const float* __restrict__ src, __half* __restrict__ dst)
{
    int i = blockIdx.x * 256 + threadIdx.x;       // float4 index
    float4 v = ((const float4*)src)[i];
    __half2* d = (__half2*)dst;
    d[2 * i]     = __floats2half2_rn(v.x, v.y);
    d[2 * i + 1] = __floats2half2_rn(v.z, v.w);
}

// ---------------- RMSNorm (optionally also emits fp16) ----------------------
__global__ __launch_bounds__(256) void rmsnorm_kernel(
    const float* __restrict__ x, const float* __restrict__ w,
    float* __restrict__ out, __half* __restrict__ outh)
{
    int t = blockIdx.x;
    const float4* xr = (const float4*)(x + (size_t)t * DD);
    float4 v = xr[threadIdx.x];
    float ss = v.x * v.x + v.y * v.y + v.z * v.z + v.w * v.w;
    #pragma unroll
    for (int o = 16; o; o >>= 1) ss += __shfl_xor_sync(0xffffffffu, ss, o);
    __shared__ float sh[8];
    __shared__ float stot;
    int warp = threadIdx.x >> 5;
    if ((threadIdx.x & 31) == 0) sh[warp] = ss;
    __syncthreads();
    if (threadIdx.x == 0) {
        float s = 0.f;
        #pragma unroll
        for (int i = 0; i < 8; i++) s += sh[i];
        stot = rsqrtf(s / (float)DD + RMS_EPS);
    }
    __syncthreads();
    float sc = stot;
    float4 wv = ((const float4*)w)[threadIdx.x];
    float4 o;
    o.x = v.x * sc * wv.x; o.y = v.y * sc * wv.y;
    o.z = v.z * sc * wv.z; o.w = v.w * sc * wv.w;
    ((float4*)(out + (size_t)t * DD))[threadIdx.x] = o;
    if (outh) {
        __half2* dh = (__half2*)(outh + (size_t)t * DD);
        dh[threadIdx.x * 2]     = __floats2half2_rn(o.x, o.y);
        dh[threadIdx.x * 2 + 1] = __floats2half2_rn(o.z, o.w);
    }
}

// ---- 3-stage issue macro for dense proj (A + B 128-row tiles) --------------
#define ISSUE_PROJ(tile, st) do {                                              \
    const int koff_ = (tile) * 32;                                             \
    const uint32_t ao_ = (uint32_t)(st) * TILEW * 4;                           \
    _Pragma("unroll")                                                          \
    for (int i_ = 0; i_ < 4; i_++) {                                           \
        cp16(dA0 + ao_ + i_ * 32 * TSTR * 4, Ap + (size_t)i_ * 32 * Kk + koff_); \
        cp16(dB0 + ao_ + i_ * 32 * TSTR * 4, Wp + (size_t)i_ * 32 * Kk + koff_); \
    }                                                                          \
    cp_commit();                                                               \
} while (0)

#define COMPUTE_TILE(Ab, Bb)                                                   \
    _Pragma("unroll")                                                          \
    for (int k8 = 0; k8 < 4; k8++) {                                           \
        int kb = k8 * 8;                                                       \
        uint32_t bf[4][2];                                                     \
        _Pragma("unroll")                                                      \
        for (int ni = 0; ni < 4; ni++) {                                       \
            int n = warpN * 32 + ni * 8 + g;                                   \
            bf[ni][0] = (Bb)[n * TSTR + kb + t];                               \
            bf[ni][1] = (Bb)[n * TSTR + kb + t + 4];                           \
        }                                                                      \
        _Pragma("unroll")                                                      \
        for (int mi = 0; mi < 4; mi++) {                                       \
            int m = warpM * 64 + mi * 16 + g;                                  \
            uint32_t af[4];                                                    \
            af[0] = (Ab)[m * TSTR + kb + t];                                   \
            af[1] = (Ab)[(m + 8) * TSTR + kb + t];                             \
            af[2] = (Ab)[m * TSTR + kb + t + 4];                               \
            af[3] = (Ab)[(m + 8) * TSTR + kb + t + 4];                         \
            _Pragma("unroll")                                                  \
            for (int ni = 0; ni < 4; ni++)                                     \
                mma_tf32(acc[mi][ni], af, bf[ni]);                             \
        }                                                                      \
    }

// ---------------- dense proj GEMM (tf32, 3-stage) ---------------------------
__global__ __launch_bounds__(256) void gemm_mma_proj3(
    const float* __restrict__ A, const float* __restrict__ W,
    const float* __restrict__ resid, float* __restrict__ C,
    int Kk, int Nn)
{
    extern __shared__ uint32_t smbuf[];
    uint32_t* As = smbuf;
    uint32_t* Bs = smbuf + 3 * TILEW;
    const uint32_t smA = (uint32_t)__cvta_generic_to_shared(As);
    const uint32_t smB = (uint32_t)__cvta_generic_to_shared(Bs);

    const int tid = threadIdx.x;
    const int lane = tid & 31, warp = tid >> 5;
    const int warpM = warp >> 2, warpN = warp & 3;
    const int g = lane >> 2, t = lane & 3;
    const int m0 = blockIdx.y * 128, n0 = blockIdx.x * 128;
    float acc[4][4][4] = {};

    const int lrow = tid >> 3;
    const int lkf = (tid & 7) * 4;
    const float* Ap = A + (size_t)(m0 + lrow) * Kk + lkf;
    const float* Wp = W + (size_t)(n0 + lrow) * Kk + lkf;
    const uint32_t dA0 = smA + (lrow * TSTR + lkf) * 4;
    const uint32_t dB0 = smB + (lrow * TSTR + lkf) * 4;

    const int nt = Kk >> 5;
    ISSUE_PROJ(0, 0);
    ISSUE_PROJ(1, 1);

    for (int kt = 0; kt < nt; kt++) {
        if (kt + 1 < nt) cp_wait<1>(); else cp_wait<0>();
        __syncthreads();
        if (kt + 2 < nt) {
            ISSUE_PROJ(kt + 2, (kt + 2) % 3);
        }
        const uint32_t* Ab = As + (kt % 3) * TILEW;
        const uint32_t* Bb = Bs + (kt % 3) * TILEW;
        COMPUTE_TILE(Ab, Bb);
    }

    #pragma unroll
    for (int mi = 0; mi < 4; mi++) {
        int r0 = m0 + warpM * 64 + mi * 16 + g;
        #pragma unroll
        for (int ni = 0; ni < 4; ni++) {
            int c = n0 + warpN * 32 + ni * 8 + 2 * t;
            size_t i0 = (size_t)r0 * Nn + c;
            size_t i1 = i0 + (size_t)8 * Nn;
            float2 v0 = make_float2(acc[mi][ni][0], acc[mi][ni][1]);
            float2 v1 = make_float2(acc[mi][ni][2], acc[mi][ni][3]);
            if (resid) {
                float2 r = *(const float2*)(resid + i0); v0.x += r.x; v0.y += r.y;
                r = *(const float2*)(resid + i1); v1.x += r.x; v1.y += r.y;
            }
            *(float2*)(C + i0) = v0;
            *(float2*)(C + i1) = v1;
        }
    }
}

// ---------------- fused QKV projection (tf32, 3-stage) ----------------------
__global__ __launch_bounds__(256) void gemm_mma_qkv(
    const float* __restrict__ A,
    const float* __restrict__ wq, const float* __restrict__ wk,
    const float* __restrict__ wv,
    float* __restrict__ qo, float* __restrict__ ko, float* __restrict__ vo)
{
    extern __shared__ uint32_t smbuf[];
    uint32_t* As = smbuf;
    uint32_t* Bs = smbuf + 3 * TILEW;
    const uint32_t smA = (uint32_t)__cvta_generic_to_shared(As);
    const uint32_t smB = (uint32_t)__cvta_generic_to_shared(Bs);

    const int tid = threadIdx.x;
    const int lane = tid & 31, warp = tid >> 5;
    const int warpM = warp >> 2, warpN = warp & 3;
    const int g = lane >> 2, t = lane & 3;
    const int m0 = blockIdx.y * 128;
    const int n0t = blockIdx.x * 128;

    const float* W; float* C; int n0;
    if (n0t < DD)            { W = wq; C = qo; n0 = n0t; }
    else if (n0t < 2 * DD)   { W = wk; C = ko; n0 = n0t - DD; }
    else                     { W = wv; C = vo; n0 = n0t - 2 * DD; }

    const int Kk = DD;
    float acc[4][4][4] = {};

    const int lrow = tid >> 3;
    const int lkf = (tid & 7) * 4;
    const float* Ap = A + (size_t)(m0 + lrow) * Kk + lkf;
    const float* Wp = W + (size_t)(n0 + lrow) * Kk + lkf;
    const uint32_t dA0 = smA + (lrow * TSTR + lkf) * 4;
    const uint32_t dB0 = smB + (lrow * TSTR + lkf) * 4;

    const int nt = Kk >> 5;
    ISSUE_PROJ(0, 0);
    ISSUE_PROJ(1, 1);

    for (int kt = 0; kt < nt; kt++) {
        if (kt + 1 < nt) cp_wait<1>(); else cp_wait<0>();
        __syncthreads();
        if (kt + 2 < nt) {
            ISSUE_PROJ(kt + 2, (kt + 2) % 3);
        }
        const uint32_t* Ab = As + (kt % 3) * TILEW;
        const uint32_t* Bb = Bs + (kt % 3) * TILEW;
        COMPUTE_TILE(Ab, Bb);
    }

    #pragma unroll
    for (int mi = 0; mi < 4; mi++) {
        int r0 = m0 + warpM * 64 + mi * 16 + g;
        #pragma unroll
        for (int ni = 0; ni < 4; ni++) {
            int c = n0 + warpN * 32 + ni * 8 + 2 * t;
            size_t i0 = (size_t)r0 * DD + c;
            size_t i1 = i0 + (size_t)8 * DD;
            *(float2*)(C + i0) = make_float2(acc[mi][ni][0], acc[mi][ni][1]);
            *(float2*)(C + i1) = make_float2(acc[mi][ni][2], acc[mi][ni][3]);
        }
    }
}

// ---------------- fused w1+w3 expert GEMM (fp16 mma, 2-stage) ---------------
// hidh[slot, n0..n0+63] = silu(A@w1h^T) * (A@w3h^T)
// grid (FF/64, NTOK/128, E), 256 threads. Warp grid 2(M) x 4(N): 64x16 per B.
__global__ __launch_bounds__(256) void moe_w13_h(const __half* __restrict__ A)
{
    const int e = blockIdx.z;
    const int count = g_expcnt[e];
    const int m0 = blockIdx.y * 128;
    if (m0 >= count) return;

    extern __shared__ uint32_t smbuf[];   // [2][W13H_STAGE]
    __shared__ int srow[128];
    const uint32_t smb = (uint32_t)__cvta_generic_to_shared(smbuf);

    const int tid = threadIdx.x;
    if (tid < 128) {
        int r = m0 + tid;
        srow[tid] = (r < count) ? g_expslots[e * NTOK + r] : -1;
    }
    __syncthreads();

    const int lane = tid & 31, warp = tid >> 5;
    const int warpM = warp >> 2, warpN = warp & 3;
    const int g = lane >> 2, t = lane & 3;
    const int n0 = blockIdx.x * 64;
    float acc1[4][2][4] = {};
    float acc3[4][2][4] = {};

    // fill assignment: A row = tid>>1 (2 16B chunks), B row = (tid&127)>>1
    const int arow_f = tid >> 1;
    const int ac = (tid & 1) * 2;           // chunk index (16 halfs per pair)
    const int s_a = srow[arow_f];
    const int aok = (s_a >= 0);
    const __half* aptr = A + (size_t)(aok ? (s_a >> 1) : 0) * DD + ac * 8;
    const int brow = (tid & 127) >> 1;
    const int bc = (tid & 1) * 2;
    const __half* bptr = ((tid < 128) ? g_w1h : g_w3h)
                         + (size_t)e * FF * DD + (size_t)(n0 + brow) * DD + bc * 8;
    const uint32_t bRegion = (tid < 128) ? (HA_TILE * 4) : ((HA_TILE + HB_TILE) * 4);
    const uint32_t dA0 = smb + (arow_f * HSTR + ac * 4) * 4;
    const uint32_t dB0 = smb + bRegion + (brow * HSTR + bc * 4) * 4;

#define ISSUE_W13H(tile, st) do {                                              \
    const int ko_ = (tile) * 32;                                               \
    const uint32_t o_ = (uint32_t)(st) * W13H_STAGE * 4;                       \
    cp16z(dA0 + o_,      aptr + ko_,     aok);                                 \
    cp16z(dA0 + o_ + 16, aptr + ko_ + 8, aok);                                 \
    cp16 (dB0 + o_,      bptr + ko_);                                          \
    cp16 (dB0 + o_ + 16, bptr + ko_ + 8);                                      \
    cp_commit();                                                               \
} while (0)

    const int nt = DD / 32;   // 32
    ISSUE_W13H(0, 0);

    for (int kt = 0; kt < nt; kt++) {
        const int buf = kt & 1;
        if (kt + 1 < nt) {
            ISSUE_W13H(kt + 1, buf ^ 1);
            cp_wait<1>();
        } else {
            cp_wait<0>();
        }
        __syncthreads();

        const uint32_t* Sb  = smbuf + buf * W13H_STAGE;
        const uint32_t* Ab  = Sb;
        const uint32_t* B1b = Sb + HA_TILE;
        const uint32_t* B3b = Sb + HA_TILE + HB_TILE;
        #pragma unroll
        for (int s = 0; s < 2; s++) {       // two k16 steps per 32-k tile
            int kb = s * 8;
            uint32_t bf1[2][2], bf3[2][2];
            #pragma unroll
            for (int ni = 0; ni < 2; ni++) {
                int n = warpN * 16 + ni * 8 + g;
                bf1[ni][0] = B1b[n * HSTR + kb + t];
                bf1[ni][1] = B1b[n * HSTR + kb + t + 4];
                bf3[ni][0] = B3b[n * HSTR + kb + t];
                bf3[ni][1] = B3b[n * HSTR + kb + t + 4];
            }
            #pragma unroll
            for (int mi = 0; mi < 4; mi++) {
                int m = warpM * 64 + mi * 16 + g;
                uint32_t af[4];
                af[0] = Ab[m * HSTR + kb + t];
                af[1] = Ab[(m + 8) * HSTR + kb + t];
                af[2] = Ab[m * HSTR + kb + t + 4];
                af[3] = Ab[(m + 8) * HSTR + kb + t + 4];
                #pragma unroll
                for (int ni = 0; ni < 2; ni++) {
                    mma_f16(acc1[mi][ni], af, bf1[ni]);
                    mma_f16(acc3[mi][ni], af, bf3[ni]);
                }
            }
        }
        __syncthreads();
    }

    // epilogue: hidh = silu(h1) * h3 (fp16)
    #pragma unroll
    for (int mi = 0; mi < 4; mi++) {
        int mloc0 = warpM * 64 + mi * 16 + g;
        #pragma unroll
        for (int half = 0; half < 2; half++) {
            int mloc = mloc0 + half * 8;
            int s = srow[mloc];
            if (s < 0) continue;
            #pragma unroll
            for (int ni = 0; ni < 2; ni++) {
                int c = n0 + warpN * 16 + ni * 8 + 2 * t;
                float h1x = acc1[mi][ni][half * 2],     h1y = acc1[mi][ni][half * 2 + 1];
                float h3x = acc3[mi][ni][half * 2],     h3y = acc3[mi][ni][half * 2 + 1];
                float ox = (h1x / (1.f + expf(-h1x))) * h3x;
                float oy = (h1y / (1.f + expf(-h1y))) * h3y;
                *(__half2*)(&g_hidh[(size_t)s * FF + c]) = __floats2half2_rn(ox, oy);
            }
        }
    }
}

// ---------------- w2 expert GEMM (fp16 mma, N=128, 2-stage) -----------------
// g_ypair[slot] = hidh[slot] @ w2h^T. grid (DD/128, NTOK/128, E), 256 threads.
__global__ __launch_bounds__(256) void moe_w2_h()
{
    const int e = blockIdx.z;
    const int count = g_expcnt[e];
    const int m0 = blockIdx.y * 128;
    if (m0 >= count) return;

    extern __shared__ uint32_t smbuf[];   // [2][W2H_STAGE]
    __shared__ int srow[128];
    const uint32_t smb = (uint32_t)__cvta_generic_to_shared(smbuf);

    const int tid = threadIdx.x;
    if (tid < 128) {
        int r = m0 + tid;
        srow[tid] = (r < count) ? g_expslots[e * NTOK + r] : -1;
    }
    __syncthreads();

    const int lane = tid & 31, warp = tid >> 5;
    const int warpM = warp >> 2, warpN = warp & 3;
    const int g = lane >> 2, t = lane & 3;
    const int n0 = blockIdx.x * 128;
    float acc[4][4][4] = {};

    const int arow_f = tid >> 1;
    const int ac = (tid & 1) * 2;
    const int s_a = srow[arow_f];
    const int aok = (s_a >= 0);
    const __half* aptr = g_hidh + (size_t)(aok ? s_a : 0) * FF + ac * 8;
    const __half* bptr = g_w2h + (size_t)e * DD * FF
                         + (size_t)(n0 + arow_f) * FF + ac * 8;
    const uint32_t dA0 = smb + (arow_f * HSTR + ac * 4) * 4;
    const uint32_t dB0 = smb + HA_TILE * 4 + (arow_f * HSTR + ac * 4) * 4;

#define ISSUE_W2H(tile, st) do {                                               \
    const int ko_ = (tile) * 32;                                               \
    const uint32_t o_ = (uint32_t)(st) * W2H_STAGE * 4;                        \
    cp16z(dA0 + o_,      aptr + ko_,     aok);                                 \
    cp16z(dA0 + o_ + 16, aptr + ko_ + 8, aok);                                 \
    cp16 (dB0 + o_,      bptr + ko_);                                          \
    cp16 (dB0 + o_ + 16, bptr + ko_ + 8);                                      \
    cp_commit();                                                               \
} while (0)

    const int nt = FF / 32;   // 128
    ISSUE_W2H(0, 0);

    for (int kt = 0; kt < nt; kt++) {
        const int buf = kt & 1;
        if (kt + 1 < nt) {
            ISSUE_W2H(kt + 1, buf ^ 1);
            cp_wait<1>();
        } else {
            cp_wait<0>();
        }
        __syncthreads();

        const uint32_t* Sb = smbuf + buf * W2H_STAGE;
        const uint32_t* Ab = Sb;
        const uint32_t* Bb = Sb + HA_TILE;
        #pragma unroll
        for (int s = 0; s < 2; s++) {
            int kb = s * 8;
            uint32_t bf[4][2];
            #pragma unroll
            for (int ni = 0; ni < 4; ni++) {
                int n = warpN * 32 + ni * 8 + g;
                bf[ni][0] = Bb[n * HSTR + kb + t];
                bf[ni][1] = Bb[n * HSTR + kb + t + 4];
            }
            #pragma unroll
            for (int mi = 0; mi < 4; mi++) {
                int m = warpM * 64 + mi * 16 + g;
                uint32_t af[4];
                af[0] = Ab[m * HSTR + kb + t];
                af[1] = Ab[(m + 8) * HSTR + kb + t];
                af[2] = Ab[m * HSTR + kb + t + 4];
                af[3] = Ab[(m + 8) * HSTR + kb + t + 4];
                #pragma unroll
                for (int ni = 0; ni < 4; ni++)
                    mma_f16(acc[mi][ni], af, bf[ni]);
            }
        }
        __syncthreads();
    }

    #pragma unroll
    for (int mi = 0; mi < 4; mi++) {
        int mloc0 = warpM * 64 + mi * 16 + g;
        #pragma unroll
        for (int half = 0; half < 2; half++) {
            int mloc = mloc0 + half * 8;
            int s = srow[mloc];
            if (s < 0) continue;
            #pragma unroll
            for (int ni = 0; ni < 4; ni++) {
                int c = n0 + warpN * 32 + ni * 8 + 2 * t;
                *(float2*)(&g_ypair[(size_t)s * DD + c]) =
                    make_float2(acc[mi][ni][half * 2], acc[mi][ni][half * 2 + 1]);
            }
        }
    }
}

// ---------------- RoPE (q and k in place) -----------------------------------
__global__ void rope_kernel(float* __restrict__ qh, float* __restrict__ kh,
                            const float* __restrict__ cosb,
                            const float* __restrict__ sinb)
{
    int idx = blockIdx.x * blockDim.x + threadIdx.x;
    int i = idx & 31;
    int th = idx >> 5;
    int t = th >> 4;
    int s = t & (SS - 1);
    float c = cosb[s * 32 + i], sn = sinb[s * 32 + i];
    size_t base = (size_t)th * HDD + i * 2;
    float xr = qh[base], xi = qh[base + 1];
    qh[base]     = xr * c - xi * sn;
    qh[base + 1] = xr * sn + xi * c;
    xr = kh[base]; xi = kh[base + 1];
    kh[base]     = xr * c - xi * sn;
    kh[base + 1] = xr * sn + xi * c;
}

// ---------------- Flash attention (tf32 tensor cores) -----------------------
#define ASTR 68
#define ATT_SMEM (4 * 64 * ASTR * 4)
__global__ __launch_bounds__(128) void attn_mma_kernel(
    const float* __restrict__ Q, const float* __restrict__ K,
    const float* __restrict__ V, float* __restrict__ O,
    const int* __restrict__ causal_flag)
{
    extern __shared__ float sm[];
    float* Qs = sm;
    float* Ks = Qs + 64 * ASTR;
    float* Vt = Ks + 64 * ASTR;
    float* Ps = Vt + 64 * ASTR;
    const int qt = blockIdx.x, bh = blockIdx.y;
    const int b = bh >> 4, h = bh & 15;
    const int tid = threadIdx.x;
    const int warp = tid >> 5, lane = tid & 31;
    const int g = lane >> 2, t = lane & 3;
    const int causal = *causal_flag;
    const size_t base = (size_t)b * SS * DD + (size_t)h * HDD;
    const float* Qb = Q + base;
    const float* Kb = K + base;
    const float* Vb = V + base;
    const int q0 = qt * 64;

    {
        int row = tid >> 1;
        int cb = (tid & 1) * 32;
        const float* src = Qb + (size_t)(q0 + row) * DD + cb;
        #pragma unroll
        for (int j = 0; j < 8; j++) {
            float4 v = *(const float4*)(src + j * 4);
            float* d = &Qs[row * ASTR + cb + j * 4];
            d[0] = v.x * ATT_SCALE; d[1] = v.y * ATT_SCALE;
            d[2] = v.z * ATT_SCALE; d[3] = v.w * ATT_SCALE;
        }
    }

    float m_run0 = -1e30f, m_run1 = -1e30f;
    float l_run0 = 0.f, l_run1 = 0.f;
    float Oacc[8][4] = {};
    const int mrow = warp * 16 + g;

    const int ktmax = causal ? qt : (SS / 64 - 1);
    for (int kt = 0; kt <= ktmax; kt++) {
        __syncthreads();
        {
            int row = tid >> 1;
            int cb = (tid & 1) * 32;
            const float* ksrc = Kb + (size_t)(kt * 64 + row) * DD + cb;
            const float* vsrc = Vb + (size_t)(kt * 64 + row) * DD + cb;
            #pragma unroll
            for (int j = 0; j < 8; j++) {
                float4 kv = *(const float4*)(ksrc + j * 4);
                float* d = &Ks[row * ASTR + cb + j * 4];
                d[0] = kv.x; d[1] = kv.y; d[2] = kv.z; d[3] = kv.w;
                float4 vv = *(const float4*)(vsrc + j * 4);
                int c = cb + j * 4;
                Vt[(c + 0) * ASTR + row] = vv.x;
                Vt[(c + 1) * ASTR + row] = vv.y;
                Vt[(c + 2) * ASTR + row] = vv.z;
                Vt[(c + 3) * ASTR + row] = vv.w;
            }
        }
        __syncthreads();

        float sacc[8][4] = {};
        const uint32_t* Qsu = (const uint32_t*)Qs;
        const uint32_t* Ksu = (const uint32_t*)Ks;
        #pragma unroll
        for (int k8 = 0; k8 < 8; k8++) {
            int kb = k8 * 8;
            uint32_t af[4];
            af[0] = Qsu[mrow * ASTR + kb + t];
            af[1] = Qsu[(mrow + 8) * ASTR + kb + t];
            af[2] = Qsu[mrow * ASTR + kb + t + 4];
            af[3] = Qsu[(mrow + 8) * ASTR + kb + t + 4];
            #pragma unroll
            for (int ni = 0; ni < 8; ni++) {
                uint32_t bf[2];
                bf[0] = Ksu[(ni * 8 + g) * ASTR + kb + t];
                bf[1] = Ksu[(ni * 8 + g) * ASTR + kb + t + 4];
                mma_tf32(sacc[ni], af, bf);
            }
        }

        const int row0 = q0 + mrow, row1 = row0 + 8;
        if (causal && kt == qt) {
            #pragma unroll
            for (int ni = 0; ni < 8; ni++) {
                int c0 = kt * 64 + ni * 8 + 2 * t;
                if (c0     > row0) sacc[ni][0] = -1e30f;
                if (c0 + 1 > row0) sacc[ni][1] = -1e30f;
                if (c0     > row1) sacc[ni][2] = -1e30f;
                if (c0 + 1 > row1) sacc[ni][3] = -1e30f;
            }
        }

        float ml0 = -1e30f, ml1 = -1e30f;
        #pragma unroll
        for (int ni = 0; ni < 8; ni++) {
            ml0 = fmaxf(ml0, fmaxf(sacc[ni][0], sacc[ni][1]));
            ml1 = fmaxf(ml1, fmaxf(sacc[ni][2], sacc[ni][3]));
        }
        ml0 = fmaxf(ml0, __shfl_xor_sync(0xffffffffu, ml0, 1));
        ml0 = fmaxf(ml0, __shfl_xor_sync(0xffffffffu, ml0, 2));
        ml1 = fmaxf(ml1, __shfl_xor_sync(0xffffffffu, ml1, 1));
        ml1 = fmaxf(ml1, __shfl_xor_sync(0xffffffffu, ml1, 2));
        float mn0 = fmaxf(m_run0, ml0), mn1 = fmaxf(m_run1, ml1);
        float a0 = expf(m_run0 - mn0), a1 = expf(m_run1 - mn1);
        float ps0 = 0.f, ps1 = 0.f;
        #pragma unroll
        for (int ni = 0; ni < 8; ni++) {
            float p0 = expf(sacc[ni][0] - mn0);
            float p1 = expf(sacc[ni][1] - mn0);
            float p2 = expf(sacc[ni][2] - mn1);
            float p3 = expf(sacc[ni][3] - mn1);
            ps0 += p0 + p1; ps1 += p2 + p3;
            int cl = ni * 8 + 2 * t;
            *(float2*)&Ps[mrow * ASTR + cl]       = make_float2(p0, p1);
            *(float2*)&Ps[(mrow + 8) * ASTR + cl] = make_float2(p2, p3);
        }
        ps0 += __shfl_xor_sync(0xffffffffu, ps0, 1);
        ps0 += __shfl_xor_sync(0xffffffffu, ps0, 2);
        ps1 += __shfl_xor_sync(0xffffffffu, ps1, 1);
        ps1 += __shfl_xor_sync(0xffffffffu, ps1, 2);
        l_run0 = l_run0 * a0 + ps0;
        l_run1 = l_run1 * a1 + ps1;
        m_run0 = mn0; m_run1 = mn1;
        #pragma unroll
        for (int ni = 0; ni < 8; ni++) {
            Oacc[ni][0] *= a0; Oacc[ni][1] *= a0;
            Oacc[ni][2] *= a1; Oacc[ni][3] *= a1;
        }
        __syncwarp();

        const uint32_t* Psu = (const uint32_t*)Ps;
        const uint32_t* Vtu = (const uint32_t*)Vt;
        #pragma unroll
        for (int k8 = 0; k8 < 8; k8++) {
            int kb = k8 * 8;
            uint32_t af[4];
            af[0] = Psu[mrow * ASTR + kb + t];
            af[1] = Psu[(mrow + 8) * ASTR + kb + t];
            af[2] = Psu[mrow * ASTR + kb + t + 4];
            af[3] = Psu[(mrow + 8) * ASTR + kb + t + 4];
            #pragma unroll
            for (int ni = 0; ni < 8; ni++) {
                uint32_t bf[2];
                bf[0] = Vtu[(ni * 8 + g) * ASTR + kb + t];
                bf[1] = Vtu[(ni * 8 + g) * ASTR + kb + t + 4];
                mma_tf32(Oacc[ni], af, bf);
            }
        }
    }

    float i0 = 1.f / l_run0, i1 = 1.f / l_run1;
    const int row0 = q0 + mrow;
    float* dst0 = O + (size_t)(b * SS + row0) * DD + (size_t)h * HDD;
    float* dst1 = dst0 + (size_t)8 * DD;
    #pragma unroll
    for (int ni = 0; ni < 8; ni++) {
        int d = ni * 8 + 2 * t;
        *(float2*)(dst0 + d) = make_float2(Oacc[ni][0] * i0, Oacc[ni][1] * i0);
        *(float2*)(dst1 + d) = make_float2(Oacc[ni][2] * i1, Oacc[ni][3] * i1);
    }
}

// ---------------- router + top-2 --------------------------------------------
__global__ void zero_counts_kernel()
{
    if (threadIdx.x < EE) g_expcnt[threadIdx.x] = 0;
}

__global__ __launch_bounds__(256) void router_kernel(
    const float* __restrict__ xn, const float* __restrict__ rw,
    const float* __restrict__ rb)
{
    int t = blockIdx.x;
    float4 xv = ((const float4*)(xn + (size_t)t * DD))[threadIdx.x];
    float lg[EE];
    #pragma unroll
    for (int e = 0; e < EE; e++) {
        float4 wv = ((const float4*)(rw + (size_t)e * DD))[threadIdx.x];
        lg[e] = xv.x * wv.x + xv.y * wv.y + xv.z * wv.z + xv.w * wv.w;
    }
    #pragma unroll
    for (int o = 16; o; o >>= 1)
        #pragma unroll
        for (int e = 0; e < EE; e++)
            lg[e] += __shfl_xor_sync(0xffffffffu, lg[e], o);
    __shared__ float sh[EE][8];
    int warp = threadIdx.x >> 5;
    if ((threadIdx.x & 31) == 0)
        #pragma unroll
        for (int e = 0; e < EE; e++) sh[e][warp] = lg[e];
    __syncthreads();
    if (threadIdx.x == 0) {
        float logits[EE];
        #pragma unroll
        for (int e = 0; e < EE; e++) {
            float s = rb[e];
            #pragma unroll
            for (int w = 0; w < 8; w++) s += sh[e][w];
            logits[e] = s;
        }
        int i0 = 0;
        #pragma unroll
        for (int e = 1; e < EE; e++) if (logits[e] > logits[i0]) i0 = e;
        int i1 = -1;
        #pragma unroll
        for (int e = 0; e < EE; e++)
            if (e != i0 && (i1 < 0 || logits[e] > logits[i1])) i1 = e;
        float ex = expf(logits[i1] - logits[i0]);
        float denom = 1.f + ex;
        float p0 = 1.f / denom, p1 = ex / denom;
        int s0 = atomicAdd(&g_expcnt[i0], 1);
        g_expslots[i0 * NTOK + s0] = 2 * t;
        g_gate[2 * t] = p0;
        int s1 = atomicAdd(&g_expcnt[i1], 1);
        g_expslots[i1 * NTOK + s1] = 2 * t + 1;
        g_gate[2 * t + 1] = p1;
    }
}

// ---------------- final combine ---------------------------------------------
__global__ __launch_bounds__(256) void combine_kernel(float* __restrict__ out)
{
    int idx = blockIdx.x * 256 + threadIdx.x;
    int t = idx >> 8;
    int col = idx & 255;
    float g0 = g_gate[2 * t], g1 = g_gate[2 * t + 1];
    float4 hv = ((const float4*)g_h)[idx];
    float4 y0 = ((const float4*)g_ypair)[(size_t)(2 * t) * 256 + col];
    float4 y1 = ((const float4*)g_ypair)[(size_t)(2 * t + 1) * 256 + col];
    float4 o;
    o.x = hv.x + g0 * y0.x + g1 * y1.x;
    o.y = hv.y + g0 * y0.y + g1 * y1.y;
    o.z = hv.z + g0 * y0.z + g1 * y1.z;
    o.w = hv.w + g0 * y0.w + g1 * y1.w;
    ((float4*)out)[idx] = o;
}

// ---------------- launch ----------------------------------------------------
extern "C" void kernel_launch(void* const* d_in, const int* in_sizes, int n_in,
                              void* d_out, int out_size)
{
    const float* q     = (const float*)d_in[0];
    const float* fcos  = (const float*)d_in[3];
    const float* fsin  = (const float*)d_in[4];
    const float* att_w = (const float*)d_in[5];
    const float* ffn_w = (const float*)d_in[6];
    const float* wq    = (const float*)d_in[7];
    const float* wk    = (const float*)d_in[8];
    const float* wv    = (const float*)d_in[9];
    const float* wo    = (const float*)d_in[10];
    const float* rw    = (const float*)d_in[11];
    const float* rb    = (const float*)d_in[12];
    const float* w1    = (const float*)d_in[13];
    const float* w2    = (const float*)d_in[14];
    const float* w3    = (const float*)d_in[15];
    const int*   causal= (const int*)d_in[16];
    float* out = (float*)d_out;

    float *p_xn, *p_qh, *p_kh, *p_vh, *p_att, *p_h;
    __half *p_w1h, *p_w3h, *p_w2h, *p_xnh;
    cudaGetSymbolAddress((void**)&p_xn, g_xn);
    cudaGetSymbolAddress((void**)&p_qh, g_qh);
    cudaGetSymbolAddress((void**)&p_kh, g_kh);
    cudaGetSymbolAddress((void**)&p_vh, g_vh);
    cudaGetSymbolAddress((void**)&p_att, g_att);
    cudaGetSymbolAddress((void**)&p_h, g_h);
    cudaGetSymbolAddress((void**)&p_w1h, g_w1h);
    cudaGetSymbolAddress((void**)&p_w3h, g_w3h);
    cudaGetSymbolAddress((void**)&p_w2h, g_w2h);
    cudaGetSymbolAddress((void**)&p_xnh, g_xnh);

    cudaFuncSetAttribute(attn_mma_kernel,
                         cudaFuncAttributeMaxDynamicSharedMemorySize, ATT_SMEM);
    cudaFuncSetAttribute(gemm_mma_proj3,
                         cudaFuncAttributeMaxDynamicSharedMemorySize, PROJ_SMEM);
    cudaFuncSetAttribute(gemm_mma_qkv,
                         cudaFuncAttributeMaxDynamicSharedMemorySize, PROJ_SMEM);
    cudaFuncSetAttribute(moe_w13_h,
                         cudaFuncAttributeMaxDynamicSharedMemorySize, W13H_SMEM);
    cudaFuncSetAttribute(moe_w2_h,
                         cudaFuncAttributeMaxDynamicSharedMemorySize, W2H_SMEM);

    // 0. weight conversions to fp16 (independent of activations)
    const int nWB = (EE * FF * DD / 4) / 256;   // 32768 blocks
    cvt_h_kernel<<<nWB, 256>>>(w1, p_w1h);
    cvt_h_kernel<<<nWB, 256>>>(w3, p_w3h);
    cvt_h_kernel<<<nWB, 256>>>(w2, p_w2h);

    // 1. qn = rmsnorm(q) * att_norm_w
    rmsnorm_kernel<<<NTOK, 256>>>(q, att_w, p_xn, (__half*)nullptr);

    // 2. fused QKV projection (tf32)
    gemm_mma_qkv<<<dim3(3 * DD / 128, NTOK / 128), 256, PROJ_SMEM>>>(
        p_xn, wq, wk, wv, p_qh, p_kh, p_vh);

    // 3. RoPE
    rope_kernel<<<(NTOK * HH * (HDD / 2)) / 256, 256>>>(p_qh, p_kh, fcos, fsin);

    // 4. flash attention (tf32)
    attn_mma_kernel<<<dim3(SS / 64, BB * HH), 128, ATT_SMEM>>>(
        p_qh, p_kh, p_vh, p_att, causal);

    // 5. h = q + att @ wo^T
    gemm_mma_proj3<<<dim3(DD / 128, NTOK / 128), 256, PROJ_SMEM>>>(
        p_att, wo, q, p_h, DD, DD);

    // 6. hn = rmsnorm(h)  (fp32 for router + fp16 for MoE GEMMs)
    rmsnorm_kernel<<<NTOK, 256>>>(p_h, ffn_w, p_xn, p_xnh);

    // 7. routing
    zero_counts_kernel<<<1, 32>>>();
    router_kernel<<<NTOK, 256>>>(p_xn, rw, rb);

    // 8. MoE on fp16 mma: fused w1+w3, then w2
    moe_w13_h<<<dim3(FF / 64, NTOK / 128, EE), 256, W13H_SMEM>>>(p_xnh);
    moe_w2_h<<<dim3(DD / 128, NTOK / 128, EE), 256, W2H_SMEM>>>();

    // 9. combine
    combine_kernel<<<NTOK, 256>>>(out);
}

// round 12
// speedup vs baseline: 2.2320x; 1.1255x over previous
#include <cuda_runtime.h>
#include <cuda_fp16.h>
#include <math.h>
#include <stdint.h>

// Problem constants
#define BB 4
#define SS 1024
#define DD 1024
#define HH 16
#define HDD 64
#define EE 8
#define FF 4096
#define NTOK 4096      // B*S
#define NSLOT 8192     // NTOK * K(=2)
#define RMS_EPS 1e-6f
#define ATT_SCALE 0.125f   // 1/sqrt(64)

// ---------------- scratch (static device globals) ---------------------------
__device__ float g_xn[NTOK * DD];
__device__ float g_qh[NTOK * DD];
__device__ float g_kh[NTOK * DD];
__device__ float g_vh[NTOK * DD];
__device__ float g_h[NTOK * DD];
__device__ float g_ypair[(size_t)NSLOT * DD];
__device__ float g_gate[NSLOT];
__device__ int   g_expcnt[EE];
__device__ int   g_expslots[EE * NTOK];
// fp16 operands
__device__ __half g_w1h[(size_t)EE * FF * DD];
__device__ __half g_w3h[(size_t)EE * FF * DD];
__device__ __half g_w2h[(size_t)EE * DD * FF];
__device__ __half g_wqh[DD * DD];
__device__ __half g_wkh[DD * DD];
__device__ __half g_wvh[DD * DD];
__device__ __half g_woh[DD * DD];
__device__ __half g_xnh[NTOK * DD];
__device__ __half g_qhh[NTOK * DD];   // rotated, pre-scaled q (fp16)
__device__ __half g_khh[NTOK * DD];   // rotated k (fp16)
__device__ __half g_vhh[NTOK * DD];
__device__ __half g_atth[NTOK * DD];  // attention output (fp16)
__device__ __half g_hidh[(size_t)NSLOT * FF];

// ---------------- helpers ---------------------------------------------------
__device__ __forceinline__ void mma_f16(float* c, const uint32_t* a, const uint32_t* b) {
    asm volatile(
        "mma.sync.aligned.m16n8k16.row.col.f32.f16.f16.f32 "
        "{%0,%1,%2,%3}, {%4,%5,%6,%7}, {%8,%9}, {%0,%1,%2,%3};\n"
        : "+f"(c[0]), "+f"(c[1]), "+f"(c[2]), "+f"(c[3])
        : "r"(a[0]), "r"(a[1]), "r"(a[2]), "r"(a[3]), "r"(b[0]), "r"(b[1]));
}

__device__ __forceinline__ void cp16(uint32_t dst, const void* src) {
    asm volatile("cp.async.cg.shared.global [%0], [%1], 16;\n"
                 :: "r"(dst), "l"(src));
}
__device__ __forceinline__ void cp16z(uint32_t dst, const void* src, int ok) {
    asm volatile("cp.async.cg.shared.global [%0], [%1], 16, %2;\n"
                 :: "r"(dst), "l"(src), "r"(ok ? 16 : 0));
}
__device__ __forceinline__ void cp_commit() {
    asm volatile("cp.async.commit_group;\n" ::: "memory");
}
template <int N>
__device__ __forceinline__ void cp_wait() {
    asm volatile("cp.async.wait_group %0;\n" :: "n"(N) : "memory");
}

// ---- fp16 smem tiles: 32-k row = 16 words, stride 20 words ------------------
#define HSTR 20
#define HA_TILE (128 * HSTR)                  // 2560 words
#define HB_TILE (64 * HSTR)                   // 1280 words
#define W13H_STAGE (HA_TILE + 2 * HB_TILE)
#define W13H_SMEM  (2 * W13H_STAGE * 4)       // 40960 B
#define PROJH_STAGE (2 * HA_TILE)             // A(128) + B(128)
#define PROJH_SMEM  (2 * PROJH_STAGE * 4)     // 40960 B

// ---------------- fp32 -> fp16 conversion ------------------------------------
__global__ __launch_bounds__(256) void cvt_h_kernel(
    const float* __restrict__ src, __half* __restrict__ dst)
{
    int i = blockIdx.x * 256 + threadIdx.x;
    float4 v = ((const float4*)src)[i];
    __half2* d = (__half2*)dst;
    d[2 * i]     = __floats2half2_rn(v.x, v.y);
    d[2 * i + 1] = __floats2half2_rn(v.z, v.w);
}

// ---------------- RMSNorm (fp32 optional + fp16 out) -------------------------
__global__ __launch_bounds__(256) void rmsnorm_kernel(
    const float* __restrict__ x, const float* __restrict__ w,
    float* __restrict__ out, __half* __restrict__ outh)
{
    int t = blockIdx.x;
    const float4* xr = (const float4*)(x + (size_t)t * DD);
    float4 v = xr[threadIdx.x];
    float ss = v.x * v.x + v.y * v.y + v.z * v.z + v.w * v.w;
    #pragma unroll
    for (int o = 16; o; o >>= 1) ss += __shfl_xor_sync(0xffffffffu, ss, o);
    __shared__ float sh[8];
    __shared__ float stot;
    int warp = threadIdx.x >> 5;
    if ((threadIdx.x & 31) == 0) sh[warp] = ss;
    __syncthreads();
    if (threadIdx.x == 0) {
        float s = 0.f;
        #pragma unroll
        for (int i = 0; i < 8; i++) s += sh[i];
        stot = rsqrtf(s / (float)DD + RMS_EPS);
    }
    __syncthreads();
    float sc = stot;
    float4 wv = ((const float4*)w)[threadIdx.x];
    float4 o;
    o.x = v.x * sc * wv.x; o.y = v.y * sc * wv.y;
    o.z = v.z * sc * wv.z; o.w = v.w * sc * wv.w;
    if (out) ((float4*)(out + (size_t)t * DD))[threadIdx.x] = o;
    __half2* dh = (__half2*)(outh + (size_t)t * DD);
    dh[threadIdx.x * 2]     = __floats2half2_rn(o.x, o.y);
    dh[threadIdx.x * 2 + 1] = __floats2half2_rn(o.z, o.w);
}

// ---------------- dense fp16 GEMM core macros --------------------------------
#define ISSUE_PROJH(tile, st) do {                                             \
    const int ko_ = (tile) * 32;                                               \
    const uint32_t o_ = (uint32_t)(st) * PROJH_STAGE * 4;                      \
    cp16(dA0 + o_,      Ap + ko_);                                             \
    cp16(dA0 + o_ + 16, Ap + ko_ + 8);                                         \
    cp16(dB0 + o_,      Bp + ko_);                                             \
    cp16(dB0 + o_ + 16, Bp + ko_ + 8);                                         \
    cp_commit();                                                               \
} while (0)

#define COMPUTE_TILE_H(Ab, Bb)                                                 \
    _Pragma("unroll")                                                          \
    for (int s = 0; s < 2; s++) {                                              \
        int kb = s * 8;                                                        \
        uint32_t bf[4][2];                                                     \
        _Pragma("unroll")                                                      \
        for (int ni = 0; ni < 4; ni++) {                                       \
            int n = warpN * 32 + ni * 8 + g;                                   \
            bf[ni][0] = (Bb)[n * HSTR + kb + t];                               \
            bf[ni][1] = (Bb)[n * HSTR + kb + t + 4];                           \
        }                                                                      \
        _Pragma("unroll")                                                      \
        for (int mi = 0; mi < 4; mi++) {                                       \
            int m = warpM * 64 + mi * 16 + g;                                  \
            uint32_t af[4];                                                    \
            af[0] = (Ab)[m * HSTR + kb + t];                                   \
            af[1] = (Ab)[(m + 8) * HSTR + kb + t];                             \
            af[2] = (Ab)[m * HSTR + kb + t + 4];                               \
            af[3] = (Ab)[(m + 8) * HSTR + kb + t + 4];                         \
            _Pragma("unroll")                                                  \
            for (int ni = 0; ni < 4; ni++)                                     \
                mma_f16(acc[mi][ni], af, bf[ni]);                              \
        }                                                                      \
    }

// ---------------- fused QKV projection (fp16 mma) ----------------------------
__global__ __launch_bounds__(256) void gemm_qkv_h(
    const __half* __restrict__ A,
    float* __restrict__ qo, float* __restrict__ ko, float* __restrict__ vo)
{
    extern __shared__ uint32_t smbuf[];
    const uint32_t smb = (uint32_t)__cvta_generic_to_shared(smbuf);
    const int tid = threadIdx.x;
    const int lane = tid & 31, warp = tid >> 5;
    const int warpM = warp >> 2, warpN = warp & 3;
    const int g = lane >> 2, t = lane & 3;
    const int m0 = blockIdx.y * 128;
    const int n0t = blockIdx.x * 128;

    const __half* W; float* C; int n0;
    if (n0t < DD)            { W = g_wqh; C = qo; n0 = n0t; }
    else if (n0t < 2 * DD)   { W = g_wkh; C = ko; n0 = n0t - DD; }
    else                     { W = g_wvh; C = vo; n0 = n0t - 2 * DD; }

    float acc[4][4][4] = {};
    const int arow_f = tid >> 1;
    const int ac = (tid & 1) * 2;
    const __half* Ap = A + (size_t)(m0 + arow_f) * DD + ac * 8;
    const __half* Bp = W + (size_t)(n0 + arow_f) * DD + ac * 8;
    const uint32_t dA0 = smb + (arow_f * HSTR + ac * 4) * 4;
    const uint32_t dB0 = smb + HA_TILE * 4 + (arow_f * HSTR + ac * 4) * 4;

    const int nt = DD / 32;
    ISSUE_PROJH(0, 0);
    for (int kt = 0; kt < nt; kt++) {
        const int buf = kt & 1;
        if (kt + 1 < nt) { ISSUE_PROJH(kt + 1, buf ^ 1); cp_wait<1>(); }
        else             { cp_wait<0>(); }
        __syncthreads();
        const uint32_t* Sb = smbuf + buf * PROJH_STAGE;
        const uint32_t* Ab = Sb;
        const uint32_t* Bb = Sb + HA_TILE;
        COMPUTE_TILE_H(Ab, Bb);
        __syncthreads();
    }

    #pragma unroll
    for (int mi = 0; mi < 4; mi++) {
        int r0 = m0 + warpM * 64 + mi * 16 + g;
        #pragma unroll
        for (int ni = 0; ni < 4; ni++) {
            int c = n0 + warpN * 32 + ni * 8 + 2 * t;
            size_t i0 = (size_t)r0 * DD + c;
            size_t i1 = i0 + (size_t)8 * DD;
            *(float2*)(C + i0) = make_float2(acc[mi][ni][0], acc[mi][ni][1]);
            *(float2*)(C + i1) = make_float2(acc[mi][ni][2], acc[mi][ni][3]);
        }
    }
}

// ---------------- wo projection (fp16 mma, fp32 resid + out) -----------------
__global__ __launch_bounds__(256) void gemm_wo_h(
    const __half* __restrict__ A, const float* __restrict__ resid,
    float* __restrict__ C)
{
    extern __shared__ uint32_t smbuf[];
    const uint32_t smb = (uint32_t)__cvta_generic_to_shared(smbuf);
    const int tid = threadIdx.x;
    const int lane = tid & 31, warp = tid >> 5;
    const int warpM = warp >> 2, warpN = warp & 3;
    const int g = lane >> 2, t = lane & 3;
    const int m0 = blockIdx.y * 128, n0 = blockIdx.x * 128;

    float acc[4][4][4] = {};
    const int arow_f = tid >> 1;
    const int ac = (tid & 1) * 2;
    const __half* Ap = A + (size_t)(m0 + arow_f) * DD + ac * 8;
    const __half* Bp = g_woh + (size_t)(n0 + arow_f) * DD + ac * 8;
    const uint32_t dA0 = smb + (arow_f * HSTR + ac * 4) * 4;
    const uint32_t dB0 = smb + HA_TILE * 4 + (arow_f * HSTR + ac * 4) * 4;

    const int nt = DD / 32;
    ISSUE_PROJH(0, 0);
    for (int kt = 0; kt < nt; kt++) {
        const int buf = kt & 1;
        if (kt + 1 < nt) { ISSUE_PROJH(kt + 1, buf ^ 1); cp_wait<1>(); }
        else             { cp_wait<0>(); }
        __syncthreads();
        const uint32_t* Sb = smbuf + buf * PROJH_STAGE;
        const uint32_t* Ab = Sb;
        const uint32_t* Bb = Sb + HA_TILE;
        COMPUTE_TILE_H(Ab, Bb);
        __syncthreads();
    }

    #pragma unroll
    for (int mi = 0; mi < 4; mi++) {
        int r0 = m0 + warpM * 64 + mi * 16 + g;
        #pragma unroll
        for (int ni = 0; ni < 4; ni++) {
            int c = n0 + warpN * 32 + ni * 8 + 2 * t;
            size_t i0 = (size_t)r0 * DD + c;
            size_t i1 = i0 + (size_t)8 * DD;
            float2 r = *(const float2*)(resid + i0);
            *(float2*)(C + i0) = make_float2(acc[mi][ni][0] + r.x,
                                             acc[mi][ni][1] + r.y);
            r = *(const float2*)(resid + i1);
            *(float2*)(C + i1) = make_float2(acc[mi][ni][2] + r.x,
                                             acc[mi][ni][3] + r.y);
        }
    }
}

// ---------------- RoPE: fp32 in -> rotated fp16 out (q pre-scaled) -----------
__global__ void rope_h_kernel(const float* __restrict__ qf,
                              const float* __restrict__ kf,
                              __half* __restrict__ qh, __half* __restrict__ kh,
                              const float* __restrict__ cosb,
                              const float* __restrict__ sinb)
{
    int idx = blockIdx.x * blockDim.x + threadIdx.x;
    int i = idx & 31;
    int th = idx >> 5;
    int t = th >> 4;
    int s = t & (SS - 1);
    float c = cosb[s * 32 + i], sn = sinb[s * 32 + i];
    size_t base = (size_t)th * HDD + i * 2;
    float xr = qf[base], xi = qf[base + 1];
    ((__half2*)qh)[base >> 1] =
        __floats2half2_rn((xr * c - xi * sn) * ATT_SCALE,
                          (xr * sn + xi * c) * ATT_SCALE);
    xr = kf[base]; xi = kf[base + 1];
    ((__half2*)kh)[base >> 1] =
        __floats2half2_rn(xr * c - xi * sn, xr * sn + xi * c);
}

// ---------------- Flash attention (fp16 mma, fp32 softmax) -------------------
#define ASTRH 36
#define ATTH_SMEM (4 * 64 * ASTRH * 4)   // 36864 B
__global__ __launch_bounds__(128) void attn_h_kernel(
    const __half* __restrict__ Q, const __half* __restrict__ K,
    const __half* __restrict__ V, __half* __restrict__ O,
    const int* __restrict__ causal_flag)
{
    extern __shared__ uint32_t smw[];
    uint32_t* Qs = smw;
    uint32_t* Ks = Qs + 64 * ASTRH;
    uint32_t* Vt = Ks + 64 * ASTRH;   // transposed halves: [d][kpos]
    uint32_t* Ps = Vt + 64 * ASTRH;
    __half* Vth = (__half*)Vt;
    const int qt = blockIdx.x, bh = blockIdx.y;
    const int b = bh >> 4, h = bh & 15;
    const int tid = threadIdx.x;
    const int warp = tid >> 5, lane = tid & 31;
    const int g = lane >> 2, t = lane & 3;
    const int causal = *causal_flag;
    const size_t base = (size_t)b * SS * DD + (size_t)h * HDD;
    const __half* Qb = Q + base;
    const __half* Kb = K + base;
    const __half* Vb = V + base;
    const int q0 = qt * 64;

    {   // load Q tile (fp16, already scaled)
        int row = tid >> 1;
        int cw = (tid & 1) * 16;
        const uint4* src = (const uint4*)(Qb + (size_t)(q0 + row) * DD + cw * 2);
        #pragma unroll
        for (int j = 0; j < 4; j++)
            *(uint4*)&Qs[row * ASTRH + cw + j * 4] = src[j];
    }

    float m_run0 = -1e30f, m_run1 = -1e30f;
    float l_run0 = 0.f, l_run1 = 0.f;
    float Oacc[8][4] = {};
    const int mrow = warp * 16 + g;

    const int ktmax = causal ? qt : (SS / 64 - 1);
    for (int kt = 0; kt <= ktmax; kt++) {
        __syncthreads();
        {   // load K tile + transposed V tile
            int row = tid >> 1;
            int cw = (tid & 1) * 16;
            const uint4* ks = (const uint4*)(Kb + (size_t)(kt * 64 + row) * DD + cw * 2);
            #pragma unroll
            for (int j = 0; j < 4; j++)
                *(uint4*)&Ks[row * ASTRH + cw + j * 4] = ks[j];
            const __half2* vs = (const __half2*)(Vb + (size_t)(kt * 64 + row) * DD + cw * 2);
            #pragma unroll
            for (int j = 0; j < 16; j++) {
                __half2 p = vs[j];
                int c = cw * 2 + j * 2;
                Vth[(c + 0) * (ASTRH * 2) + row] = __low2half(p);
                Vth[(c + 1) * (ASTRH * 2) + row] = __high2half(p);
            }
        }
        __syncthreads();

        // S = Q @ K^T
        float sacc[8][4] = {};
        #pragma unroll
        for (int s = 0; s < 4; s++) {
            int kb = s * 8;
            uint32_t af[4];
            af[0] = Qs[mrow * ASTRH + kb + t];
            af[1] = Qs[(mrow + 8) * ASTRH + kb + t];
            af[2] = Qs[mrow * ASTRH + kb + t + 4];
            af[3] = Qs[(mrow + 8) * ASTRH + kb + t + 4];
            #pragma unroll
            for (int ni = 0; ni < 8; ni++) {
                uint32_t bf[2];
                bf[0] = Ks[(ni * 8 + g) * ASTRH + kb + t];
                bf[1] = Ks[(ni * 8 + g) * ASTRH + kb + t + 4];
                mma_f16(sacc[ni], af, bf);
            }
        }

        const int row0 = q0 + mrow, row1 = row0 + 8;
        if (causal && kt == qt) {
            #pragma unroll
            for (int ni = 0; ni < 8; ni++) {
                int c0 = kt * 64 + ni * 8 + 2 * t;
                if (c0     > row0) sacc[ni][0] = -1e30f;
                if (c0 + 1 > row0) sacc[ni][1] = -1e30f;
                if (c0     > row1) sacc[ni][2] = -1e30f;
                if (c0 + 1 > row1) sacc[ni][3] = -1e30f;
            }
        }

        float ml0 = -1e30f, ml1 = -1e30f;
        #pragma unroll
        for (int ni = 0; ni < 8; ni++) {
            ml0 = fmaxf(ml0, fmaxf(sacc[ni][0], sacc[ni][1]));
            ml1 = fmaxf(ml1, fmaxf(sacc[ni][2], sacc[ni][3]));
        }
        ml0 = fmaxf(ml0, __shfl_xor_sync(0xffffffffu, ml0, 1));
        ml0 = fmaxf(ml0, __shfl_xor_sync(0xffffffffu, ml0, 2));
        ml1 = fmaxf(ml1, __shfl_xor_sync(0xffffffffu, ml1, 1));
        ml1 = fmaxf(ml1, __shfl_xor_sync(0xffffffffu, ml1, 2));
        float mn0 = fmaxf(m_run0, ml0), mn1 = fmaxf(m_run1, ml1);
        float a0 = expf(m_run0 - mn0), a1 = expf(m_run1 - mn1);
        float ps0 = 0.f, ps1 = 0.f;
        #pragma unroll
        for (int ni = 0; ni < 8; ni++) {
            float p0 = expf(sacc[ni][0] - mn0);
            float p1 = expf(sacc[ni][1] - mn0);
            float p2 = expf(sacc[ni][2] - mn1);
            float p3 = expf(sacc[ni][3] - mn1);
            ps0 += p0 + p1; ps1 += p2 + p3;
            __half2 hp0 = __floats2half2_rn(p0, p1);
            __half2 hp1 = __floats2half2_rn(p2, p3);
            Ps[mrow * ASTRH + ni * 4 + t]       = *(uint32_t*)&hp0;
            Ps[(mrow + 8) * ASTRH + ni * 4 + t] = *(uint32_t*)&hp1;
        }
        ps0 += __shfl_xor_sync(0xffffffffu, ps0, 1);
        ps0 += __shfl_xor_sync(0xffffffffu, ps0, 2);
        ps1 += __shfl_xor_sync(0xffffffffu, ps1, 1);
        ps1 += __shfl_xor_sync(0xffffffffu, ps1, 2);
        l_run0 = l_run0 * a0 + ps0;
        l_run1 = l_run1 * a1 + ps1;
        m_run0 = mn0; m_run1 = mn1;
        #pragma unroll
        for (int ni = 0; ni < 8; ni++) {
            Oacc[ni][0] *= a0; Oacc[ni][1] *= a0;
            Oacc[ni][2] *= a1; Oacc[ni][3] *= a1;
        }
        __syncwarp();

        // O += P @ V
        #pragma unroll
        for (int s = 0; s < 4; s++) {
            int kb = s * 8;
            uint32_t af[4];
            af[0] = Ps[mrow * ASTRH + kb + t];
            af[1] = Ps[(mrow + 8) * ASTRH + kb + t];
            af[2] = Ps[mrow * ASTRH + kb + t + 4];
            af[3] = Ps[(mrow + 8) * ASTRH + kb + t + 4];
            #pragma unroll
            for (int ni = 0; ni < 8; ni++) {
                uint32_t bf[2];
                bf[0] = Vt[(ni * 8 + g) * ASTRH + kb + t];
                bf[1] = Vt[(ni * 8 + g) * ASTRH + kb + t + 4];
                mma_f16(Oacc[ni], af, bf);
            }
        }
    }

    float i0 = 1.f / l_run0, i1 = 1.f / l_run1;
    const int row0 = q0 + mrow;
    __half* dst0 = O + (size_t)(b * SS + row0) * DD + (size_t)h * HDD;
    __half* dst1 = dst0 + (size_t)8 * DD;
    #pragma unroll
    for (int ni = 0; ni < 8; ni++) {
        int d = ni * 8 + 2 * t;
        *(__half2*)(dst0 + d) = __floats2half2_rn(Oacc[ni][0] * i0, Oacc[ni][1] * i0);
        *(__half2*)(dst1 + d) = __floats2half2_rn(Oacc[ni][2] * i1, Oacc[ni][3] * i1);
    }
}

// ---------------- fused w1+w3 expert GEMM (fp16 mma) -------------------------
__global__ __launch_bounds__(256) void moe_w13_h(const __half* __restrict__ A)
{
    const int e = blockIdx.z;
    const int count = g_expcnt[e];
    const int m0 = blockIdx.y * 128;
    if (m0 >= count) return;

    extern __shared__ uint32_t smbuf[];
    __shared__ int srow[128];
    const uint32_t smb = (uint32_t)__cvta_generic_to_shared(smbuf);

    const int tid = threadIdx.x;
    if (tid < 128) {
        int r = m0 + tid;
        srow[tid] = (r < count) ? g_expslots[e * NTOK + r] : -1;
    }
    __syncthreads();

    const int lane = tid & 31, warp = tid >> 5;
    const int warpM = warp >> 2, warpN = warp & 3;
    const int g = lane >> 2, t = lane & 3;
    const int n0 = blockIdx.x * 64;
    float acc1[4][2][4] = {};
    float acc3[4][2][4] = {};

    const int arow_f = tid >> 1;
    const int ac = (tid & 1) * 2;
    const int s_a = srow[arow_f];
    const int aok = (s_a >= 0);
    const __half* aptr = A + (size_t)(aok ? (s_a >> 1) : 0) * DD + ac * 8;
    const int brow = (tid & 127) >> 1;
    const int bc = (tid & 1) * 2;
    const __half* bptr = ((tid < 128) ? g_w1h : g_w3h)
                         + (size_t)e * FF * DD + (size_t)(n0 + brow) * DD + bc * 8;
    const uint32_t bRegion = (tid < 128) ? (HA_TILE * 4) : ((HA_TILE + HB_TILE) * 4);
    const uint32_t dA0 = smb + (arow_f * HSTR + ac * 4) * 4;
    const uint32_t dB0 = smb + bRegion + (brow * HSTR + bc * 4) * 4;

#define ISSUE_W13H(tile, st) do {                                              \
    const int ko_ = (tile) * 32;                                               \
    const uint32_t o_ = (uint32_t)(st) * W13H_STAGE * 4;                       \
    cp16z(dA0 + o_,      aptr + ko_,     aok);                                 \
    cp16z(dA0 + o_ + 16, aptr + ko_ + 8, aok);                                 \
    cp16 (dB0 + o_,      bptr + ko_);                                          \
    cp16 (dB0 + o_ + 16, bptr + ko_ + 8);                                      \
    cp_commit();                                                               \
} while (0)

    const int nt = DD / 32;
    ISSUE_W13H(0, 0);
    for (int kt = 0; kt < nt; kt++) {
        const int buf = kt & 1;
        if (kt + 1 < nt) { ISSUE_W13H(kt + 1, buf ^ 1); cp_wait<1>(); }
        else             { cp_wait<0>(); }
        __syncthreads();

        const uint32_t* Sb  = smbuf + buf * W13H_STAGE;
        const uint32_t* Ab  = Sb;
        const uint32_t* B1b = Sb + HA_TILE;
        const uint32_t* B3b = Sb + HA_TILE + HB_TILE;
        #pragma unroll
        for (int s = 0; s < 2; s++) {
            int kb = s * 8;
            uint32_t bf1[2][2], bf3[2][2];
            #pragma unroll
            for (int ni = 0; ni < 2; ni++) {
                int n = warpN * 16 + ni * 8 + g;
                bf1[ni][0] = B1b[n * HSTR + kb + t];
                bf1[ni][1] = B1b[n * HSTR + kb + t + 4];
                bf3[ni][0] = B3b[n * HSTR + kb + t];
                bf3[ni][1] = B3b[n * HSTR + kb + t + 4];
            }
            #pragma unroll
            for (int mi = 0; mi < 4; mi++) {
                int m = warpM * 64 + mi * 16 + g;
                uint32_t af[4];
                af[0] = Ab[m * HSTR + kb + t];
                af[1] = Ab[(m + 8) * HSTR + kb + t];
                af[2] = Ab[m * HSTR + kb + t + 4];
                af[3] = Ab[(m + 8) * HSTR + kb + t + 4];
                #pragma unroll
                for (int ni = 0; ni < 2; ni++) {
                    mma_f16(acc1[mi][ni], af, bf1[ni]);
                    mma_f16(acc3[mi][ni], af, bf3[ni]);
                }
            }
        }
        __syncthreads();
    }

    #pragma unroll
    for (int mi = 0; mi < 4; mi++) {
        int mloc0 = warpM * 64 + mi * 16 + g;
        #pragma unroll
        for (int half = 0; half < 2; half++) {
            int mloc = mloc0 + half * 8;
            int s = srow[mloc];
            if (s < 0) continue;
            #pragma unroll
            for (int ni = 0; ni < 2; ni++) {
                int c = n0 + warpN * 16 + ni * 8 + 2 * t;
                float h1x = acc1[mi][ni][half * 2],     h1y = acc1[mi][ni][half * 2 + 1];
                float h3x = acc3[mi][ni][half * 2],     h3y = acc3[mi][ni][half * 2 + 1];
                float ox = (h1x / (1.f + expf(-h1x))) * h3x;
                float oy = (h1y / (1.f + expf(-h1y))) * h3y;
                *(__half2*)(&g_hidh[(size_t)s * FF + c]) = __floats2half2_rn(ox, oy);
            }
        }
    }
}

// ---------------- w2 expert GEMM (fp16 mma, N=128) ---------------------------
__global__ __launch_bounds__(256) void moe_w2_h()
{
    const int e = blockIdx.z;
    const int count = g_expcnt[e];
    const int m0 = blockIdx.y * 128;
    if (m0 >= count) return;

    extern __shared__ uint32_t smbuf[];
    __shared__ int srow[128];
    const uint32_t smb = (uint32_t)__cvta_generic_to_shared(smbuf);

    const int tid = threadIdx.x;
    if (tid < 128) {
        int r = m0 + tid;
        srow[tid] = (r < count) ? g_expslots[e * NTOK + r] : -1;
    }
    __syncthreads();

    const int lane = tid & 31, warp = tid >> 5;
    const int warpM = warp >> 2, warpN = warp & 3;
    const int g = lane >> 2, t = lane & 3;
    const int n0 = blockIdx.x * 128;
    float acc[4][4][4] = {};

    const int arow_f = tid >> 1;
    const int ac = (tid & 1) * 2;
    const int s_a = srow[arow_f];
    const int aok = (s_a >= 0);
    const __half* aptr = g_hidh + (size_t)(aok ? s_a : 0) * FF + ac * 8;
    const __half* bptr = g_w2h + (size_t)e * DD * FF
                         + (size_t)(n0 + arow_f) * FF + ac * 8;
    const uint32_t dA0 = smb + (arow_f * HSTR + ac * 4) * 4;
    const uint32_t dB0 = smb + HA_TILE * 4 + (arow_f * HSTR + ac * 4) * 4;

#define ISSUE_W2H(tile, st) do {                                               \
    const int ko_ = (tile) * 32;                                               \
    const uint32_t o_ = (uint32_t)(st) * PROJH_STAGE * 4;                      \
    cp16z(dA0 + o_,      aptr + ko_,     aok);                                 \
    cp16z(dA0 + o_ + 16, aptr + ko_ + 8, aok);                                 \
    cp16 (dB0 + o_,      bptr + ko_);                                          \
    cp16 (dB0 + o_ + 16, bptr + ko_ + 8);                                      \
    cp_commit();                                                               \
} while (0)

    const int nt = FF / 32;
    ISSUE_W2H(0, 0);
    for (int kt = 0; kt < nt; kt++) {
        const int buf = kt & 1;
        if (kt + 1 < nt) { ISSUE_W2H(kt + 1, buf ^ 1); cp_wait<1>(); }
        else             { cp_wait<0>(); }
        __syncthreads();

        const uint32_t* Sb = smbuf + buf * PROJH_STAGE;
        const uint32_t* Ab = Sb;
        const uint32_t* Bb = Sb + HA_TILE;
        COMPUTE_TILE_H(Ab, Bb);
        __syncthreads();
    }

    #pragma unroll
    for (int mi = 0; mi < 4; mi++) {
        int mloc0 = warpM * 64 + mi * 16 + g;
        #pragma unroll
        for (int half = 0; half < 2; half++) {
            int mloc = mloc0 + half * 8;
            int s = srow[mloc];
            if (s < 0) continue;
            #pragma unroll
            for (int ni = 0; ni < 4; ni++) {
                int c = n0 + warpN * 32 + ni * 8 + 2 * t;
                *(float2*)(&g_ypair[(size_t)s * DD + c]) =
                    make_float2(acc[mi][ni][half * 2], acc[mi][ni][half * 2 + 1]);
            }
        }
    }
}

// ---------------- router + top-2 ---------------------------------------------
__global__ void zero_counts_kernel()
{
    if (threadIdx.x < EE) g_expcnt[threadIdx.x] = 0;
}

__global__ __launch_bounds__(256) void router_kernel(
    const float* __restrict__ xn, const float* __restrict__ rw,
    const float* __restrict__ rb)
{
    int t = blockIdx.x;
    float4 xv = ((const float4*)(xn + (size_t)t * DD))[threadIdx.x];
    float lg[EE];
    #pragma unroll
    for (int e = 0; e < EE; e++) {
        float4 wv = ((const float4*)(rw + (size_t)e * DD))[threadIdx.x];
        lg[e] = xv.x * wv.x + xv.y * wv.y + xv.z * wv.z + xv.w * wv.w;
    }
    #pragma unroll
    for (int o = 16; o; o >>= 1)
        #pragma unroll
        for (int e = 0; e < EE; e++)
            lg[e] += __shfl_xor_sync(0xffffffffu, lg[e], o);
    __shared__ float sh[EE][8];
    int warp = threadIdx.x >> 5;
    if ((threadIdx.x & 31) == 0)
        #pragma unroll
        for (int e = 0; e < EE; e++) sh[e][warp] = lg[e];
    __syncthreads();
    if (threadIdx.x == 0) {
        float logits[EE];
        #pragma unroll
        for (int e = 0; e < EE; e++) {
            float s = rb[e];
            #pragma unroll
            for (int w = 0; w < 8; w++) s += sh[e][w];
            logits[e] = s;
        }
        int i0 = 0;
        #pragma unroll
        for (int e = 1; e < EE; e++) if (logits[e] > logits[i0]) i0 = e;
        int i1 = -1;
        #pragma unroll
        for (int e = 0; e < EE; e++)
            if (e != i0 && (i1 < 0 || logits[e] > logits[i1])) i1 = e;
        float ex = expf(logits[i1] - logits[i0]);
        float denom = 1.f + ex;
        float p0 = 1.f / denom, p1 = ex / denom;
        int s0 = atomicAdd(&g_expcnt[i0], 1);
        g_expslots[i0 * NTOK + s0] = 2 * t;
        g_gate[2 * t] = p0;
        int s1 = atomicAdd(&g_expcnt[i1], 1);
        g_expslots[i1 * NTOK + s1] = 2 * t + 1;
        g_gate[2 * t + 1] = p1;
    }
}

// ---------------- final combine ----------------------------------------------
__global__ __launch_bounds__(256) void combine_kernel(float* __restrict__ out)
{
    int idx = blockIdx.x * 256 + threadIdx.x;
    int t = idx >> 8;
    int col = idx & 255;
    float g0 = g_gate[2 * t], g1 = g_gate[2 * t + 1];
    float4 hv = ((const float4*)g_h)[idx];
    float4 y0 = ((const float4*)g_ypair)[(size_t)(2 * t) * 256 + col];
    float4 y1 = ((const float4*)g_ypair)[(size_t)(2 * t + 1) * 256 + col];
    float4 o;
    o.x = hv.x + g0 * y0.x + g1 * y1.x;
    o.y = hv.y + g0 * y0.y + g1 * y1.y;
    o.z = hv.z + g0 * y0.z + g1 * y1.z;
    o.w = hv.w + g0 * y0.w + g1 * y1.w;
    ((float4*)out)[idx] = o;
}

// ---------------- launch -----------------------------------------------------
extern "C" void kernel_launch(void* const* d_in, const int* in_sizes, int n_in,
                              void* d_out, int out_size)
{
    const float* q     = (const float*)d_in[0];
    const float* fcos  = (const float*)d_in[3];
    const float* fsin  = (const float*)d_in[4];
    const float* att_w = (const float*)d_in[5];
    const float* ffn_w = (const float*)d_in[6];
    const float* wq    = (const float*)d_in[7];
    const float* wk    = (const float*)d_in[8];
    const float* wv    = (const float*)d_in[9];
    const float* wo    = (const float*)d_in[10];
    const float* rw    = (const float*)d_in[11];
    const float* rb    = (const float*)d_in[12];
    const float* w1    = (const float*)d_in[13];
    const float* w2    = (const float*)d_in[14];
    const float* w3    = (const float*)d_in[15];
    const int*   causal= (const int*)d_in[16];
    float* out = (float*)d_out;

    float *p_xn, *p_qh, *p_kh, *p_vh, *p_h;
    __half *p_w1h, *p_w3h, *p_w2h, *p_xnh;
    __half *p_wqh, *p_wkh, *p_wvh, *p_woh;
    __half *p_qhh, *p_khh, *p_vhh, *p_atth;
    cudaGetSymbolAddress((void**)&p_xn, g_xn);
    cudaGetSymbolAddress((void**)&p_qh, g_qh);
    cudaGetSymbolAddress((void**)&p_kh, g_kh);
    cudaGetSymbolAddress((void**)&p_vh, g_vh);
    cudaGetSymbolAddress((void**)&p_h, g_h);
    cudaGetSymbolAddress((void**)&p_w1h, g_w1h);
    cudaGetSymbolAddress((void**)&p_w3h, g_w3h);
    cudaGetSymbolAddress((void**)&p_w2h, g_w2h);
    cudaGetSymbolAddress((void**)&p_xnh, g_xnh);
    cudaGetSymbolAddress((void**)&p_wqh, g_wqh);
    cudaGetSymbolAddress((void**)&p_wkh, g_wkh);
    cudaGetSymbolAddress((void**)&p_wvh, g_wvh);
    cudaGetSymbolAddress((void**)&p_woh, g_woh);
    cudaGetSymbolAddress((void**)&p_qhh, g_qhh);
    cudaGetSymbolAddress((void**)&p_khh, g_khh);
    cudaGetSymbolAddress((void**)&p_vhh, g_vhh);
    cudaGetSymbolAddress((void**)&p_atth, g_atth);

    cudaFuncSetAttribute(attn_h_kernel,
                         cudaFuncAttributeMaxDynamicSharedMemorySize, ATTH_SMEM);
    cudaFuncSetAttribute(gemm_qkv_h,
                         cudaFuncAttributeMaxDynamicSharedMemorySize, PROJH_SMEM);
    cudaFuncSetAttribute(gemm_wo_h,
                         cudaFuncAttributeMaxDynamicSharedMemorySize, PROJH_SMEM);
    cudaFuncSetAttribute(moe_w13_h,
                         cudaFuncAttributeMaxDynamicSharedMemorySize, W13H_SMEM);
    cudaFuncSetAttribute(moe_w2_h,
                         cudaFuncAttributeMaxDynamicSharedMemorySize, PROJH_SMEM);

    // 0. weight conversions to fp16
    const int nWB = (EE * FF * DD / 4) / 256;
    cvt_h_kernel<<<nWB, 256>>>(w1, p_w1h);
    cvt_h_kernel<<<nWB, 256>>>(w3, p_w3h);
    cvt_h_kernel<<<nWB, 256>>>(w2, p_w2h);
    const int nDB = (DD * DD / 4) / 256;
    cvt_h_kernel<<<nDB, 256>>>(wq, p_wqh);
    cvt_h_kernel<<<nDB, 256>>>(wk, p_wkh);
    cvt_h_kernel<<<nDB, 256>>>(wv, p_wvh);
    cvt_h_kernel<<<nDB, 256>>>(wo, p_woh);

    // 1. qn = rmsnorm(q) -> fp16
    rmsnorm_kernel<<<NTOK, 256>>>(q, att_w, (float*)nullptr, p_xnh);

    // 2. fused QKV projection (fp16 mma, fp32 out)
    gemm_qkv_h<<<dim3(3 * DD / 128, NTOK / 128), 256, PROJH_SMEM>>>(
        p_xnh, p_qh, p_kh, p_vh);

    // 3. RoPE -> fp16 (q pre-scaled); v -> fp16
    rope_h_kernel<<<(NTOK * HH * (HDD / 2)) / 256, 256>>>(
        p_qh, p_kh, p_qhh, p_khh, fcos, fsin);
    cvt_h_kernel<<<(NTOK * DD / 4) / 256, 256>>>(p_vh, p_vhh);

    // 4. flash attention (fp16 mma) -> fp16 out
    attn_h_kernel<<<dim3(SS / 64, BB * HH), 128, ATTH_SMEM>>>(
        p_qhh, p_khh, p_vhh, p_atth, causal);

    // 5. h = q + att @ wo^T
    gemm_wo_h<<<dim3(DD / 128, NTOK / 128), 256, PROJH_SMEM>>>(
        p_atth, q, p_h);

    // 6. hn = rmsnorm(h)
    rmsnorm_kernel<<<NTOK, 256>>>(p_h, ffn_w, p_xn, p_xnh);

    // 7. routing
    zero_counts_kernel<<<1, 32>>>();
    router_kernel<<<NTOK, 256>>>(p_xn, rw, rb);

    // 8. MoE (fp16 mma)
    moe_w13_h<<<dim3(FF / 64, NTOK / 128, EE), 256, W13H_SMEM>>>(p_xnh);
    moe_w2_h<<<dim3(DD / 128, NTOK / 128, EE), 256, PROJH_SMEM>>>();

    // 9. combine
    combine_kernel<<<NTOK, 256>>>(out);
}